// round 3
// baseline (speedup 1.0000x reference)
#include <cuda_runtime.h>
#include <cuda_bf16.h>
#include <math.h>

// Problem constants
#define S 2048
#define C 2048
#define H 16
#define D 128
#define FF 8192
#define EPS 1e-6f

// ---------------------------------------------------------------------------
// Scratch (static device globals -- no runtime allocation allowed)
// ---------------------------------------------------------------------------
__device__ float g_xn[S * C];      // rmsnorm1 output
__device__ float g_q[S * C];
__device__ float g_k[S * C];
__device__ float g_v[S * C];
__device__ float g_k2[H * S];      // per-head per-key ||k||^2 (post-RoPE)
__device__ float g_ctx[S * C];
__device__ float g_h[S * C];       // residual 1
__device__ float g_y[S * C];       // rmsnorm2 output
__device__ float g_gate[S * FF];
__device__ float g_up[S * FF];

// ---------------------------------------------------------------------------
// packed f32x2 helpers (FFMA2: 2x fp32 FMA per instruction on sm_103a)
// ---------------------------------------------------------------------------
__device__ __forceinline__ unsigned long long pack_f2(float x, float y) {
    unsigned long long r;
    asm("mov.b64 %0, {%1, %2};" : "=l"(r) : "f"(x), "f"(y));
    return r;
}
__device__ __forceinline__ float2 unpack_f2(unsigned long long u) {
    float2 r;
    asm("mov.b64 {%0, %1}, %2;" : "=f"(r.x), "=f"(r.y) : "l"(u));
    return r;
}
__device__ __forceinline__ void ffma2(unsigned long long& d,
                                      unsigned long long a,
                                      unsigned long long b) {
    asm("fma.rn.f32x2 %0, %1, %2, %0;" : "+l"(d) : "l"(a), "l"(b));
}

// ---------------------------------------------------------------------------
// RMSNorm: out[row] = x[row] * rsqrt(mean(x^2) + eps) * w
// grid = S rows, 256 threads
// ---------------------------------------------------------------------------
__global__ void rmsnorm_kernel(const float* __restrict__ x,
                               const float* __restrict__ w,
                               float* __restrict__ out) {
    const int row = blockIdx.x;
    const float* xr = x + (size_t)row * C;
    float s = 0.f;
    for (int c = threadIdx.x; c < C; c += blockDim.x) {
        float v = xr[c];
        s += v * v;
    }
#pragma unroll
    for (int off = 16; off; off >>= 1) s += __shfl_xor_sync(0xffffffffu, s, off);
    __shared__ float sh[8];
    if ((threadIdx.x & 31) == 0) sh[threadIdx.x >> 5] = s;
    __syncthreads();
    __shared__ float inv_s;
    if (threadIdx.x == 0) {
        float t = 0.f;
#pragma unroll
        for (int i = 0; i < 8; ++i) t += sh[i];
        inv_s = rsqrtf(t * (1.0f / C) + EPS);
    }
    __syncthreads();
    const float inv = inv_s;
    float* orow = out + (size_t)row * C;
    for (int c = threadIdx.x; c < C; c += blockDim.x)
        orow[c] = xr[c] * inv * w[c];
}

// ---------------------------------------------------------------------------
// SGEMM (NT): Cmat[M,N] = A[M,K] * B[N,K]^T (+ addend)
// A,B row-major. 128x128 tile, BK=8, 8x8 per thread, f32x2 packed FMA.
// All dims multiples of 128. 256 threads.
// ---------------------------------------------------------------------------
#define BM 128
#define BN 128
#define BK 8

__global__ __launch_bounds__(256) void sgemm_nt(const float* __restrict__ A,
                                                const float* __restrict__ B,
                                                float* __restrict__ Cmat,
                                                const float* __restrict__ addend,
                                                int M, int N, int K) {
    __shared__ unsigned long long As2[BK][BM];    // (a,a) duplicated pairs: 8KB
    __shared__ __align__(16) float Bs[BK][BN];    // 4KB

    const int tid = threadIdx.x;
    const int m0 = blockIdx.y * BM;
    const int n0 = blockIdx.x * BN;

    // loader mapping: each thread brings one float4 of A and of B per chunk
    const int lr = tid >> 1;          // 0..127
    const int lc = (tid & 1) * 4;     // 0 or 4
    const float* Ap = A + (size_t)(m0 + lr) * K + lc;
    const float* Bp = B + (size_t)(n0 + lr) * K + lc;

    const int tx = tid & 15;          // 0..15 -> n sub-tile
    const int ty = tid >> 4;          // 0..15 -> m sub-tile

    unsigned long long acc[8][4];
#pragma unroll
    for (int i = 0; i < 8; ++i)
#pragma unroll
        for (int j = 0; j < 4; ++j) acc[i][j] = 0ull;

    for (int kk = 0; kk < K; kk += BK) {
        float4 av = *reinterpret_cast<const float4*>(Ap + kk);
        float4 bv = *reinterpret_cast<const float4*>(Bp + kk);
        As2[lc + 0][lr] = pack_f2(av.x, av.x);
        As2[lc + 1][lr] = pack_f2(av.y, av.y);
        As2[lc + 2][lr] = pack_f2(av.z, av.z);
        As2[lc + 3][lr] = pack_f2(av.w, av.w);
        Bs[lc + 0][lr] = bv.x;
        Bs[lc + 1][lr] = bv.y;
        Bs[lc + 2][lr] = bv.z;
        Bs[lc + 3][lr] = bv.w;
        __syncthreads();

#pragma unroll
        for (int k = 0; k < BK; ++k) {
            unsigned long long a2[8];
#pragma unroll
            for (int ii = 0; ii < 8; ++ii) a2[ii] = As2[k][ty * 8 + ii];
            unsigned long long b2[4];
            const unsigned long long* bp =
                reinterpret_cast<const unsigned long long*>(&Bs[k][tx * 8]);
#pragma unroll
            for (int jj = 0; jj < 4; ++jj) b2[jj] = bp[jj];
#pragma unroll
            for (int ii = 0; ii < 8; ++ii)
#pragma unroll
                for (int jj = 0; jj < 4; ++jj) ffma2(acc[ii][jj], a2[ii], b2[jj]);
        }
        __syncthreads();
    }

#pragma unroll
    for (int ii = 0; ii < 8; ++ii) {
        const int row = m0 + ty * 8 + ii;
        float* crow = Cmat + (size_t)row * N + n0 + tx * 8;
        const float* arow =
            addend ? (addend + (size_t)row * N + n0 + tx * 8) : nullptr;
#pragma unroll
        for (int jj = 0; jj < 4; ++jj) {
            float2 vv = unpack_f2(acc[ii][jj]);
            if (arow) {
                vv.x += arow[2 * jj];
                vv.y += arow[2 * jj + 1];
            }
            *reinterpret_cast<float2*>(&crow[2 * jj]) = vv;
        }
    }
}

// ---------------------------------------------------------------------------
// RoPE (in place) on [S, H, D] laid out as [S, C]; optionally emit ||k||^2.
// grid (S, H), 64 threads: thread t handles dims t and t+64.
// ---------------------------------------------------------------------------
__global__ void rope_kernel(float* __restrict__ x,
                            const float* __restrict__ cosb,
                            const float* __restrict__ sinb,
                            float* __restrict__ k2out) {
    const int s = blockIdx.x, h = blockIdx.y, t = threadIdx.x;
    float* row = x + (size_t)s * C + h * D;
    const float x1 = row[t], x2 = row[t + 64];
    const float c1 = cosb[s * D + t], s1 = sinb[s * D + t];
    const float c2 = cosb[s * D + t + 64], s2 = sinb[s * D + t + 64];
    const float o1 = x1 * c1 - x2 * s1;   // rot = [-x2, x1]
    const float o2 = x2 * c2 + x1 * s2;
    row[t] = o1;
    row[t + 64] = o2;
    if (k2out) {
        float ss = o1 * o1 + o2 * o2;
#pragma unroll
        for (int off = 16; off; off >>= 1)
            ss += __shfl_xor_sync(0xffffffffu, ss, off);
        __shared__ float sh[2];
        if ((t & 31) == 0) sh[t >> 5] = ss;
        __syncthreads();
        if (t == 0) k2out[(size_t)h * S + s] = sh[0] + sh[1];
    }
}

// ---------------------------------------------------------------------------
// Flash attention (causal, Gaussian kernel). q^2 term cancels in softmax:
// logit = (q.k)/sqrt(D) - k2/(2 sqrt(D)).
// One warp per query row; 8 warps per block. grid (S/8, H).
// ---------------------------------------------------------------------------
__global__ __launch_bounds__(256) void attn_kernel(const float* __restrict__ q,
                                                   const float* __restrict__ k,
                                                   const float* __restrict__ v,
                                                   const float* __restrict__ k2,
                                                   float* __restrict__ ctx) {
    const int h = blockIdx.y;
    const int i = blockIdx.x * 8 + (threadIdx.x >> 5);
    const int lane = threadIdx.x & 31;
    const float invS = 0.08838834764831845f;  // 1/sqrt(128)
    const float hInv = 0.5f * invS;

    const float* qr = q + (size_t)i * C + h * D;
    const float q0 = qr[lane], q1 = qr[lane + 32];
    const float q2v = qr[lane + 64], q3 = qr[lane + 96];

    const float* kb = k + h * D;
    const float* vb = v + h * D;
    const float* k2b = k2 + (size_t)h * S;

    float m = -1e30f, l = 0.f;
    float a0 = 0.f, a1 = 0.f, a2 = 0.f, a3 = 0.f;

    for (int j = 0; j <= i; ++j) {
        const float* kr = kb + (size_t)j * C;
        float s = q0 * kr[lane] + q1 * kr[lane + 32] + q2v * kr[lane + 64] +
                  q3 * kr[lane + 96];
#pragma unroll
        for (int off = 16; off; off >>= 1)
            s += __shfl_xor_sync(0xffffffffu, s, off);
        const float logit = s * invS - k2b[j] * hInv;
        const float mn = fmaxf(m, logit);
        const float sc = __expf(m - mn);
        const float p = __expf(logit - mn);
        l = l * sc + p;
        const float* vr = vb + (size_t)j * C;
        a0 = a0 * sc + p * vr[lane];
        a1 = a1 * sc + p * vr[lane + 32];
        a2 = a2 * sc + p * vr[lane + 64];
        a3 = a3 * sc + p * vr[lane + 96];
        m = mn;
    }
    const float inv = 1.f / l;
    float* cr = ctx + (size_t)i * C + h * D;
    cr[lane] = a0 * inv;
    cr[lane + 32] = a1 * inv;
    cr[lane + 64] = a2 * inv;
    cr[lane + 96] = a3 * inv;
}

// ---------------------------------------------------------------------------
// SiLU(gate) * up, in place into gate
// ---------------------------------------------------------------------------
__global__ void silu_mul_kernel(float* __restrict__ gate,
                                const float* __restrict__ up, int n) {
    int idx = blockIdx.x * blockDim.x + threadIdx.x;
    if (idx < n) {
        float g = gate[idx];
        float u = up[idx];
        float sg = 1.f / (1.f + __expf(-g));
        gate[idx] = g * sg * u;
    }
}

// ---------------------------------------------------------------------------
// launch
// ---------------------------------------------------------------------------
extern "C" void kernel_launch(void* const* d_in, const int* in_sizes, int n_in,
                              void* d_out, int out_size) {
    const float* hidden = (const float*)d_in[0];
    const float* cosb   = (const float*)d_in[1];
    const float* sinb   = (const float*)d_in[2];
    // d_in[3] = attention_mask: exactly causal, handled analytically
    const float* ln1_w  = (const float*)d_in[4];
    const float* wq     = (const float*)d_in[5];
    const float* wk     = (const float*)d_in[6];
    const float* wv     = (const float*)d_in[7];
    const float* wo     = (const float*)d_in[8];
    const float* ln2_w  = (const float*)d_in[9];
    const float* wgate  = (const float*)d_in[10];
    const float* wup    = (const float*)d_in[11];
    const float* wdown  = (const float*)d_in[12];
    float* out = (float*)d_out;

    float *xn, *q, *k, *v, *k2, *ctx, *hbuf, *y, *gate, *up;
    cudaGetSymbolAddress((void**)&xn, g_xn);
    cudaGetSymbolAddress((void**)&q, g_q);
    cudaGetSymbolAddress((void**)&k, g_k);
    cudaGetSymbolAddress((void**)&v, g_v);
    cudaGetSymbolAddress((void**)&k2, g_k2);
    cudaGetSymbolAddress((void**)&ctx, g_ctx);
    cudaGetSymbolAddress((void**)&hbuf, g_h);
    cudaGetSymbolAddress((void**)&y, g_y);
    cudaGetSymbolAddress((void**)&gate, g_gate);
    cudaGetSymbolAddress((void**)&up, g_up);

    // 1. input RMSNorm
    rmsnorm_kernel<<<S, 256>>>(hidden, ln1_w, xn);

    // 2. Q, K, V projections
    dim3 gqkv(C / BN, S / BM);
    sgemm_nt<<<gqkv, 256>>>(xn, wq, q, nullptr, S, C, C);
    sgemm_nt<<<gqkv, 256>>>(xn, wk, k, nullptr, S, C, C);
    sgemm_nt<<<gqkv, 256>>>(xn, wv, v, nullptr, S, C, C);

    // 3. RoPE (k also emits ||k||^2)
    dim3 grope(S, H);
    rope_kernel<<<grope, 64>>>(q, cosb, sinb, nullptr);
    rope_kernel<<<grope, 64>>>(k, cosb, sinb, k2);

    // 4. attention
    dim3 gattn(S / 8, H);
    attn_kernel<<<gattn, 256>>>(q, k, v, k2, ctx);

    // 5. output projection + residual: h = hidden + ctx @ wo^T
    sgemm_nt<<<gqkv, 256>>>(ctx, wo, hbuf, hidden, S, C, C);

    // 6. post-attn RMSNorm
    rmsnorm_kernel<<<S, 256>>>(hbuf, ln2_w, y);

    // 7. FFN gate & up
    dim3 gff(FF / BN, S / BM);
    sgemm_nt<<<gff, 256>>>(y, wgate, gate, nullptr, S, FF, C);
    sgemm_nt<<<gff, 256>>>(y, wup, up, nullptr, S, FF, C);

    // 8. SiLU(gate) * up
    silu_mul_kernel<<<(S * FF + 255) / 256, 256>>>(gate, up, S * FF);

    // 9. down projection + residual -> final output
    dim3 gdown(C / BN, S / BM);
    sgemm_nt<<<gdown, 256>>>(gate, wdown, out, hbuf, S, C, FF);
}

// round 5
// speedup vs baseline: 1.8825x; 1.8825x over previous
#include <cuda_runtime.h>
#include <cuda_bf16.h>
#include <math.h>
#include <stdint.h>

#define S 2048
#define C 2048
#define H 16
#define D 128
#define FF 8192
#define EPS 1e-6f

// GEMM tiling: 128x128 CTA tile, BK=64 bf16 (128B rows), 3-stage cp.async pipe
#define NS 3
#define TILE_B 16384              // 128 rows x 128 bytes
#define STAGE_B (4 * TILE_B)      // Ah, Al, Bh, Bl
#define GSMEM (NS * STAGE_B)      // 196608 bytes

// ---------------------------------------------------------------------------
// Static device scratch
// ---------------------------------------------------------------------------
__device__ float g_q[S * C], g_k[S * C], g_v[S * C];
__device__ float g_ctx[S * C], g_h[S * C];
__device__ float g_gate[S * FF], g_up[S * FF];
__device__ float g_k2[H * S];
__device__ __nv_bfloat16 g_xnH[S * C], g_xnL[S * C];
__device__ __nv_bfloat16 g_yH[S * C], g_yL[S * C];
__device__ __nv_bfloat16 g_cH[S * C], g_cL[S * C];
__device__ __nv_bfloat16 g_aH[S * FF], g_aL[S * FF];
__device__ __nv_bfloat16 g_wqH[C * C], g_wqL[C * C];
__device__ __nv_bfloat16 g_wkH[C * C], g_wkL[C * C];
__device__ __nv_bfloat16 g_wvH[C * C], g_wvL[C * C];
__device__ __nv_bfloat16 g_woH[C * C], g_woL[C * C];
__device__ __nv_bfloat16 g_wgH[FF * C], g_wgL[FF * C];
__device__ __nv_bfloat16 g_wuH[FF * C], g_wuL[FF * C];
__device__ __nv_bfloat16 g_wdH[C * FF], g_wdL[C * FF];

// ---------------------------------------------------------------------------
// PTX helpers (baseline ISA only -- no arch-specific 'a' instructions)
// ---------------------------------------------------------------------------
__device__ __forceinline__ uint32_t smem_u32(const void* p) {
    uint32_t a;
    asm("{ .reg .u64 t; cvta.to.shared.u64 t, %1; cvt.u32.u64 %0, t; }"
        : "=r"(a) : "l"(p));
    return a;
}
__device__ __forceinline__ void cpa16(uint32_t d, const void* s) {
    asm volatile("cp.async.cg.shared.global [%0], [%1], 16;"
                 :: "r"(d), "l"(s) : "memory");
}
__device__ __forceinline__ void cpa_commit() {
    asm volatile("cp.async.commit_group;" ::: "memory");
}
__device__ __forceinline__ void cpa_wait1() {
    asm volatile("cp.async.wait_group 1;" ::: "memory");
}
__device__ __forceinline__ void ldsm4(uint32_t* r, uint32_t addr) {
    asm volatile(
        "ldmatrix.sync.aligned.m8n8.x4.shared.b16 {%0,%1,%2,%3}, [%4];"
        : "=r"(r[0]), "=r"(r[1]), "=r"(r[2]), "=r"(r[3]) : "r"(addr));
}
__device__ __forceinline__ void mma16816(float* c, const uint32_t* a,
                                         const uint32_t* b) {
    asm volatile(
        "mma.sync.aligned.m16n8k16.row.col.f32.bf16.bf16.f32 "
        "{%0,%1,%2,%3}, {%4,%5,%6,%7}, {%8,%9}, {%0,%1,%2,%3};"
        : "+f"(c[0]), "+f"(c[1]), "+f"(c[2]), "+f"(c[3])
        : "r"(a[0]), "r"(a[1]), "r"(a[2]), "r"(a[3]), "r"(b[0]), "r"(b[1]));
}

// ---------------------------------------------------------------------------
// GEMM (NT): Cout[M,N] = (Ah+Al)[M,K] @ (Bh+Bl)[N,K]^T (+ addend), fp32 out.
// split-bf16 3-MMA: hh + hl + lh. 8 warps: 2(m) x 4(n), each warp 64x32.
// ---------------------------------------------------------------------------
__global__ __launch_bounds__(256, 1) void gemm_split(
    const __nv_bfloat16* __restrict__ Ah, const __nv_bfloat16* __restrict__ Al,
    const __nv_bfloat16* __restrict__ Bh, const __nv_bfloat16* __restrict__ Bl,
    float* __restrict__ Cout, const float* __restrict__ addend,
    int M, int N, int K) {
    extern __shared__ __align__(1024) char smem[];
    const uint32_t sb = smem_u32(smem);
    const int tid = threadIdx.x;
    const int wid = tid >> 5, lid = tid & 31;
    const int m0 = blockIdx.y * 128, n0 = blockIdx.x * 128;
    const int NC = K >> 6;

    // ---- loader mapping: thread -> row (0..127), 4 consecutive 16B chunks
    const int lrow = tid >> 1;
    const int lc0 = (tid & 1) * 4;  // 16B-chunk index 0..7
    const __nv_bfloat16* pAh = Ah + (size_t)(m0 + lrow) * K + lc0 * 8;
    const __nv_bfloat16* pAl = Al + (size_t)(m0 + lrow) * K + lc0 * 8;
    const __nv_bfloat16* pBh = Bh + (size_t)(n0 + lrow) * K + lc0 * 8;
    const __nv_bfloat16* pBl = Bl + (size_t)(n0 + lrow) * K + lc0 * 8;
    uint32_t soff[4];
#pragma unroll
    for (int i = 0; i < 4; ++i) {
        uint32_t b = lrow * 128 + (lc0 + i) * 16;
        soff[i] = b ^ ((b >> 3) & 0x70);  // SW128 swizzle
    }

#define LOAD_STAGE(st, c)                                                   \
    do {                                                                    \
        uint32_t base = sb + (uint32_t)(st) * STAGE_B;                      \
        size_t g = (size_t)(c) * 64;                                        \
        _Pragma("unroll") for (int i = 0; i < 4; ++i) {                     \
            cpa16(base + soff[i], pAh + g + i * 8);                         \
            cpa16(base + TILE_B + soff[i], pAl + g + i * 8);                \
            cpa16(base + 2 * TILE_B + soff[i], pBh + g + i * 8);            \
            cpa16(base + 3 * TILE_B + soff[i], pBl + g + i * 8);            \
        }                                                                   \
    } while (0)

    // ---- fragment addressing (ldmatrix lane maps)
    // A frag (m16k16): lane -> row = lid&15, k-half = lid>>4
    // B frag (two n8-tiles): lane -> nrow = (lid&7)|((lid>>4)<<3), k-half=(lid>>3)&1
    const int rowA = lid & 15, khA = lid >> 4;
    const int rowB = (lid & 7) | (((lid >> 4) & 1) << 3), khB = (lid >> 3) & 1;
    const uint32_t rbA = (uint32_t)(((wid & 1) * 64 + rowA) * 128);
    const uint32_t rbB = (uint32_t)(((wid >> 1) * 32 + rowB) * 128);
    const uint32_t xrA = (uint32_t)((rowA & 7) << 4);
    const uint32_t xrB = (uint32_t)((rowB & 7) << 4);
    uint32_t offA[4], offB[4];
#pragma unroll
    for (int ks = 0; ks < 4; ++ks) {
        offA[ks] = (uint32_t)(ks * 32 + khA * 16) ^ xrA;
        offB[ks] = (uint32_t)(ks * 32 + khB * 16) ^ xrB;
    }

    float acc[4][4][4];
#pragma unroll
    for (int i = 0; i < 4; ++i)
#pragma unroll
        for (int j = 0; j < 4; ++j)
#pragma unroll
            for (int r = 0; r < 4; ++r) acc[i][j][r] = 0.f;

    // ---- prologue: stages 0,1
    LOAD_STAGE(0, 0);
    cpa_commit();
    LOAD_STAGE(1, 1);
    cpa_commit();

    for (int c = 0; c < NC; ++c) {
        const int st = c % NS;
        cpa_wait1();
        __syncthreads();
        if (c + 2 < NC) LOAD_STAGE((c + 2) % NS, c + 2);
        cpa_commit();

        const uint32_t base = sb + (uint32_t)st * STAGE_B;
        const uint32_t aH = base + rbA;
        const uint32_t aL = base + TILE_B + rbA;
        const uint32_t bH = base + 2 * TILE_B + rbB;
        const uint32_t bL = base + 3 * TILE_B + rbB;

#pragma unroll
        for (int ks = 0; ks < 4; ++ks) {
            uint32_t fah[4][4], fal[4][4];
#pragma unroll
            for (int mi = 0; mi < 4; ++mi) {
                ldsm4(fah[mi], aH + mi * 2048 + offA[ks]);
                ldsm4(fal[mi], aL + mi * 2048 + offA[ks]);
            }
            uint32_t fbh[2][4], fbl[2][4];
#pragma unroll
            for (int p = 0; p < 2; ++p) {
                ldsm4(fbh[p], bH + p * 2048 + offB[ks]);
                ldsm4(fbl[p], bL + p * 2048 + offB[ks]);
            }
#pragma unroll
            for (int mi = 0; mi < 4; ++mi) {
#pragma unroll
                for (int ni = 0; ni < 4; ++ni) {
                    const int p = ni >> 1, hf = (ni & 1) * 2;
                    mma16816(acc[mi][ni], fah[mi], &fbh[p][hf]);  // hh
                    mma16816(acc[mi][ni], fah[mi], &fbl[p][hf]);  // hl
                    mma16816(acc[mi][ni], fal[mi], &fbh[p][hf]);  // lh
                }
            }
        }
    }

    // ---- epilogue
    const int q = lid >> 2, l = lid & 3;
    const int wm0 = m0 + (wid & 1) * 64;
    const int wn0 = n0 + (wid >> 1) * 32;
#pragma unroll
    for (int mi = 0; mi < 4; ++mi) {
#pragma unroll
        for (int ni = 0; ni < 4; ++ni) {
            const int r0 = wm0 + mi * 16 + q;
            const int cc = wn0 + ni * 8 + 2 * l;
            float2 v0 = make_float2(acc[mi][ni][0], acc[mi][ni][1]);
            float2 v1 = make_float2(acc[mi][ni][2], acc[mi][ni][3]);
            if (addend) {
                const float2 a0 =
                    *reinterpret_cast<const float2*>(addend + (size_t)r0 * N + cc);
                const float2 a1 = *reinterpret_cast<const float2*>(
                    addend + (size_t)(r0 + 8) * N + cc);
                v0.x += a0.x; v0.y += a0.y;
                v1.x += a1.x; v1.y += a1.y;
            }
            *reinterpret_cast<float2*>(Cout + (size_t)r0 * N + cc) = v0;
            *reinterpret_cast<float2*>(Cout + (size_t)(r0 + 8) * N + cc) = v1;
        }
    }
}

// ---------------------------------------------------------------------------
// fp32 -> (bf16 hi, bf16 lo) split
// ---------------------------------------------------------------------------
__device__ __forceinline__ void split1(float v, __nv_bfloat16& h, __nv_bfloat16& l) {
    h = __float2bfloat16(v);
    l = __float2bfloat16(v - __bfloat162float(h));
}

__global__ void split_kernel(const float* __restrict__ x,
                             __nv_bfloat16* __restrict__ oh,
                             __nv_bfloat16* __restrict__ ol, int n) {
    int i = blockIdx.x * blockDim.x + threadIdx.x;
    if (i < n) split1(x[i], oh[i], ol[i]);
}

__global__ void rmsnorm_split(const float* __restrict__ x,
                              const float* __restrict__ w,
                              __nv_bfloat16* __restrict__ oh,
                              __nv_bfloat16* __restrict__ ol) {
    const int row = blockIdx.x;
    const float* xr = x + (size_t)row * C;
    float s = 0.f;
    for (int c = threadIdx.x; c < C; c += blockDim.x) {
        float v = xr[c];
        s += v * v;
    }
#pragma unroll
    for (int off = 16; off; off >>= 1) s += __shfl_xor_sync(0xffffffffu, s, off);
    __shared__ float sh[8];
    if ((threadIdx.x & 31) == 0) sh[threadIdx.x >> 5] = s;
    __syncthreads();
    __shared__ float inv_s;
    if (threadIdx.x == 0) {
        float t = 0.f;
#pragma unroll
        for (int i = 0; i < 8; ++i) t += sh[i];
        inv_s = rsqrtf(t * (1.0f / C) + EPS);
    }
    __syncthreads();
    const float inv = inv_s;
    for (int c = threadIdx.x; c < C; c += blockDim.x) {
        float v = xr[c] * inv * w[c];
        split1(v, oh[(size_t)row * C + c], ol[(size_t)row * C + c]);
    }
}

__global__ void silu_mul_split(const float* __restrict__ gate,
                               const float* __restrict__ up,
                               __nv_bfloat16* __restrict__ oh,
                               __nv_bfloat16* __restrict__ ol, int n) {
    int i = blockIdx.x * blockDim.x + threadIdx.x;
    if (i < n) {
        float g = gate[i];
        float v = g / (1.f + __expf(-g)) * up[i];
        split1(v, oh[i], ol[i]);
    }
}

// ---------------------------------------------------------------------------
// RoPE (in place, fp32), optional ||k||^2
// ---------------------------------------------------------------------------
__global__ void rope_kernel(float* __restrict__ x, const float* __restrict__ cosb,
                            const float* __restrict__ sinb,
                            float* __restrict__ k2out) {
    const int s = blockIdx.x, h = blockIdx.y, t = threadIdx.x;
    float* row = x + (size_t)s * C + h * D;
    const float x1 = row[t], x2 = row[t + 64];
    const float o1 = x1 * cosb[s * D + t] - x2 * sinb[s * D + t];
    const float o2 = x2 * cosb[s * D + t + 64] + x1 * sinb[s * D + t + 64];
    row[t] = o1;
    row[t + 64] = o2;
    if (k2out) {
        float ss = o1 * o1 + o2 * o2;
#pragma unroll
        for (int off = 16; off; off >>= 1) ss += __shfl_xor_sync(0xffffffffu, ss, off);
        __shared__ float sh[2];
        if ((t & 31) == 0) sh[t >> 5] = ss;
        __syncthreads();
        if (t == 0) k2out[(size_t)h * S + s] = sh[0] + sh[1];
    }
}

// ---------------------------------------------------------------------------
// Flash attention (causal, Gaussian kernel; q^2 cancels under softmax):
// logit = (q.k)/sqrt(D) - k2/(2 sqrt(D)). One warp per query row.
// ---------------------------------------------------------------------------
__global__ __launch_bounds__(256) void attn_kernel(const float* __restrict__ q,
                                                   const float* __restrict__ k,
                                                   const float* __restrict__ v,
                                                   const float* __restrict__ k2,
                                                   float* __restrict__ ctx) {
    const int h = blockIdx.y;
    const int i = blockIdx.x * 8 + (threadIdx.x >> 5);
    const int lane = threadIdx.x & 31;
    const float invS = 0.08838834764831845f;
    const float hInv = 0.5f * invS;

    const float* qr = q + (size_t)i * C + h * D;
    const float q0 = qr[lane], q1 = qr[lane + 32];
    const float q2v = qr[lane + 64], q3 = qr[lane + 96];
    const float* kb = k + h * D;
    const float* vb = v + h * D;
    const float* k2b = k2 + (size_t)h * S;

    float m = -1e30f, l = 0.f, a0 = 0.f, a1 = 0.f, a2 = 0.f, a3 = 0.f;
    for (int j = 0; j <= i; ++j) {
        const float* kr = kb + (size_t)j * C;
        float s = q0 * kr[lane] + q1 * kr[lane + 32] + q2v * kr[lane + 64] +
                  q3 * kr[lane + 96];
#pragma unroll
        for (int off = 16; off; off >>= 1) s += __shfl_xor_sync(0xffffffffu, s, off);
        const float logit = s * invS - k2b[j] * hInv;
        const float mn = fmaxf(m, logit);
        const float sc = __expf(m - mn);
        const float p = __expf(logit - mn);
        l = l * sc + p;
        const float* vr = vb + (size_t)j * C;
        a0 = a0 * sc + p * vr[lane];
        a1 = a1 * sc + p * vr[lane + 32];
        a2 = a2 * sc + p * vr[lane + 64];
        a3 = a3 * sc + p * vr[lane + 96];
        m = mn;
    }
    const float inv = 1.f / l;
    float* cr = ctx + (size_t)i * C + h * D;
    cr[lane] = a0 * inv;
    cr[lane + 32] = a1 * inv;
    cr[lane + 64] = a2 * inv;
    cr[lane + 96] = a3 * inv;
}

// ---------------------------------------------------------------------------
// launch
// ---------------------------------------------------------------------------
static inline float* sym(const void* s) {
    void* p = nullptr;
    cudaGetSymbolAddress(&p, s);
    return (float*)p;
}

extern "C" void kernel_launch(void* const* d_in, const int* in_sizes, int n_in,
                              void* d_out, int out_size) {
    const float* hidden = (const float*)d_in[0];
    const float* cosb = (const float*)d_in[1];
    const float* sinb = (const float*)d_in[2];
    // d_in[3] attention_mask: exactly causal, handled analytically
    const float* ln1_w = (const float*)d_in[4];
    const float* wq = (const float*)d_in[5];
    const float* wk = (const float*)d_in[6];
    const float* wv = (const float*)d_in[7];
    const float* wo = (const float*)d_in[8];
    const float* ln2_w = (const float*)d_in[9];
    const float* wg = (const float*)d_in[10];
    const float* wu = (const float*)d_in[11];
    const float* wd = (const float*)d_in[12];
    float* out = (float*)d_out;

    cudaFuncSetAttribute(gemm_split, cudaFuncAttributeMaxDynamicSharedMemorySize,
                         GSMEM);

    float* q = sym(&g_q);
    float* k = sym(&g_k);
    float* v = sym(&g_v);
    float* ctx = sym(&g_ctx);
    float* hb = sym(&g_h);
    float* gate = sym(&g_gate);
    float* up = sym(&g_up);
    float* k2 = sym(&g_k2);
    __nv_bfloat16* xnH = (__nv_bfloat16*)sym(&g_xnH);
    __nv_bfloat16* xnL = (__nv_bfloat16*)sym(&g_xnL);
    __nv_bfloat16* yH = (__nv_bfloat16*)sym(&g_yH);
    __nv_bfloat16* yL = (__nv_bfloat16*)sym(&g_yL);
    __nv_bfloat16* cH = (__nv_bfloat16*)sym(&g_cH);
    __nv_bfloat16* cL = (__nv_bfloat16*)sym(&g_cL);
    __nv_bfloat16* aH = (__nv_bfloat16*)sym(&g_aH);
    __nv_bfloat16* aL = (__nv_bfloat16*)sym(&g_aL);
    __nv_bfloat16* wqH = (__nv_bfloat16*)sym(&g_wqH);
    __nv_bfloat16* wqL = (__nv_bfloat16*)sym(&g_wqL);
    __nv_bfloat16* wkH = (__nv_bfloat16*)sym(&g_wkH);
    __nv_bfloat16* wkL = (__nv_bfloat16*)sym(&g_wkL);
    __nv_bfloat16* wvH = (__nv_bfloat16*)sym(&g_wvH);
    __nv_bfloat16* wvL = (__nv_bfloat16*)sym(&g_wvL);
    __nv_bfloat16* woH = (__nv_bfloat16*)sym(&g_woH);
    __nv_bfloat16* woL = (__nv_bfloat16*)sym(&g_woL);
    __nv_bfloat16* wgH = (__nv_bfloat16*)sym(&g_wgH);
    __nv_bfloat16* wgL = (__nv_bfloat16*)sym(&g_wgL);
    __nv_bfloat16* wuH = (__nv_bfloat16*)sym(&g_wuH);
    __nv_bfloat16* wuL = (__nv_bfloat16*)sym(&g_wuL);
    __nv_bfloat16* wdH = (__nv_bfloat16*)sym(&g_wdH);
    __nv_bfloat16* wdL = (__nv_bfloat16*)sym(&g_wdL);

    const int TPB = 256;
    // weight splits
    split_kernel<<<(C * C + TPB - 1) / TPB, TPB>>>(wq, wqH, wqL, C * C);
    split_kernel<<<(C * C + TPB - 1) / TPB, TPB>>>(wk, wkH, wkL, C * C);
    split_kernel<<<(C * C + TPB - 1) / TPB, TPB>>>(wv, wvH, wvL, C * C);
    split_kernel<<<(C * C + TPB - 1) / TPB, TPB>>>(wo, woH, woL, C * C);
    split_kernel<<<(FF * C + TPB - 1) / TPB, TPB>>>(wg, wgH, wgL, FF * C);
    split_kernel<<<(FF * C + TPB - 1) / TPB, TPB>>>(wu, wuH, wuL, FF * C);
    split_kernel<<<(C * FF + TPB - 1) / TPB, TPB>>>(wd, wdH, wdL, C * FF);

    // 1. input RMSNorm (split output)
    rmsnorm_split<<<S, 256>>>(hidden, ln1_w, xnH, xnL);

    // 2. QKV projections (tensor-core split-bf16)
    dim3 gqkv(C / 128, S / 128);
    gemm_split<<<gqkv, 256, GSMEM>>>(xnH, xnL, wqH, wqL, q, nullptr, S, C, C);
    gemm_split<<<gqkv, 256, GSMEM>>>(xnH, xnL, wkH, wkL, k, nullptr, S, C, C);
    gemm_split<<<gqkv, 256, GSMEM>>>(xnH, xnL, wvH, wvL, v, nullptr, S, C, C);

    // 3. RoPE
    dim3 grope(S, H);
    rope_kernel<<<grope, 64>>>(q, cosb, sinb, nullptr);
    rope_kernel<<<grope, 64>>>(k, cosb, sinb, k2);

    // 4. attention
    dim3 gattn(S / 8, H);
    attn_kernel<<<gattn, 256>>>(q, k, v, k2, ctx);

    // 5. output projection + residual
    split_kernel<<<(S * C + TPB - 1) / TPB, TPB>>>(ctx, cH, cL, S * C);
    gemm_split<<<gqkv, 256, GSMEM>>>(cH, cL, woH, woL, hb, hidden, S, C, C);

    // 6. post-attn RMSNorm
    rmsnorm_split<<<S, 256>>>(hb, ln2_w, yH, yL);

    // 7. FFN gate & up
    dim3 gff(FF / 128, S / 128);
    gemm_split<<<gff, 256, GSMEM>>>(yH, yL, wgH, wgL, gate, nullptr, S, FF, C);
    gemm_split<<<gff, 256, GSMEM>>>(yH, yL, wuH, wuL, up, nullptr, S, FF, C);

    // 8. SiLU(gate)*up -> split
    silu_mul_split<<<(S * FF + TPB - 1) / TPB, TPB>>>(gate, up, aH, aL, S * FF);

    // 9. down projection + residual -> final output
    dim3 gdown(C / 128, S / 128);
    gemm_split<<<gdown, 256, GSMEM>>>(aH, aL, wdH, wdL, out, hb, S, C, FF);
}

// round 6
// speedup vs baseline: 3.5745x; 1.8988x over previous
#include <cuda_runtime.h>
#include <cuda_bf16.h>
#include <math.h>
#include <stdint.h>

#define S 2048
#define C 2048
#define H 16
#define D 128
#define FF 8192
#define EPS 1e-6f

// GEMM tiling: 128x128 CTA tile, BK=64 bf16 (128B rows), 3-stage cp.async pipe
#define NS 3
#define TILE_B 16384              // 128 rows x 128 bytes
#define STAGE_B (4 * TILE_B)      // Ah, Al, Bh, Bl
#define GSMEM (NS * STAGE_B)      // 196608 bytes

// Attention smem: Q(4 units) + K(4) + V(4) + bias
#define ASMEM (12 * TILE_B + 512)

// ---------------------------------------------------------------------------
// Static device scratch
// ---------------------------------------------------------------------------
__device__ float g_q[S * C], g_k[S * C], g_v[S * C];
__device__ float g_ctx[S * C], g_h[S * C];
__device__ float g_gate[S * FF], g_up[S * FF];
__device__ float g_k2[H * S];
__device__ __nv_bfloat16 g_qH[S * C], g_qL[S * C];
__device__ __nv_bfloat16 g_kH[S * C], g_kL[S * C];
__device__ __nv_bfloat16 g_vtH[C * S], g_vtL[C * S];
__device__ __nv_bfloat16 g_xnH[S * C], g_xnL[S * C];
__device__ __nv_bfloat16 g_yH[S * C], g_yL[S * C];
__device__ __nv_bfloat16 g_cH[S * C], g_cL[S * C];
__device__ __nv_bfloat16 g_aH[S * FF], g_aL[S * FF];
__device__ __nv_bfloat16 g_wqH[C * C], g_wqL[C * C];
__device__ __nv_bfloat16 g_wkH[C * C], g_wkL[C * C];
__device__ __nv_bfloat16 g_wvH[C * C], g_wvL[C * C];
__device__ __nv_bfloat16 g_woH[C * C], g_woL[C * C];
__device__ __nv_bfloat16 g_wgH[FF * C], g_wgL[FF * C];
__device__ __nv_bfloat16 g_wuH[FF * C], g_wuL[FF * C];
__device__ __nv_bfloat16 g_wdH[C * FF], g_wdL[C * FF];

// ---------------------------------------------------------------------------
// PTX helpers (baseline ISA only)
// ---------------------------------------------------------------------------
__device__ __forceinline__ uint32_t smem_u32(const void* p) {
    uint32_t a;
    asm("{ .reg .u64 t; cvta.to.shared.u64 t, %1; cvt.u32.u64 %0, t; }"
        : "=r"(a) : "l"(p));
    return a;
}
__device__ __forceinline__ void cpa16(uint32_t d, const void* s) {
    asm volatile("cp.async.cg.shared.global [%0], [%1], 16;"
                 :: "r"(d), "l"(s) : "memory");
}
__device__ __forceinline__ void cpa_commit() {
    asm volatile("cp.async.commit_group;" ::: "memory");
}
__device__ __forceinline__ void cpa_wait1() {
    asm volatile("cp.async.wait_group 1;" ::: "memory");
}
__device__ __forceinline__ void cpa_wait0() {
    asm volatile("cp.async.wait_group 0;" ::: "memory");
}
__device__ __forceinline__ void ldsm4(uint32_t* r, uint32_t addr) {
    asm volatile(
        "ldmatrix.sync.aligned.m8n8.x4.shared.b16 {%0,%1,%2,%3}, [%4];"
        : "=r"(r[0]), "=r"(r[1]), "=r"(r[2]), "=r"(r[3]) : "r"(addr));
}
__device__ __forceinline__ void mma16816(float* c, const uint32_t* a,
                                         const uint32_t* b) {
    asm volatile(
        "mma.sync.aligned.m16n8k16.row.col.f32.bf16.bf16.f32 "
        "{%0,%1,%2,%3}, {%4,%5,%6,%7}, {%8,%9}, {%0,%1,%2,%3};"
        : "+f"(c[0]), "+f"(c[1]), "+f"(c[2]), "+f"(c[3])
        : "r"(a[0]), "r"(a[1]), "r"(a[2]), "r"(a[3]), "r"(b[0]), "r"(b[1]));
}
__device__ __forceinline__ uint32_t pack_bf2(float x, float y) {
    __nv_bfloat162 t = __floats2bfloat162_rn(x, y);
    return *reinterpret_cast<uint32_t*>(&t);
}

// ---------------------------------------------------------------------------
// GEMM (NT): Cout[M,N] = (Ah+Al)[M,K] @ (Bh+Bl)[N,K]^T (+ addend), fp32 out.
// ---------------------------------------------------------------------------
__global__ __launch_bounds__(256, 1) void gemm_split(
    const __nv_bfloat16* __restrict__ Ah, const __nv_bfloat16* __restrict__ Al,
    const __nv_bfloat16* __restrict__ Bh, const __nv_bfloat16* __restrict__ Bl,
    float* __restrict__ Cout, const float* __restrict__ addend,
    int M, int N, int K) {
    extern __shared__ __align__(1024) char smem[];
    const uint32_t sb = smem_u32(smem);
    const int tid = threadIdx.x;
    const int wid = tid >> 5, lid = tid & 31;
    const int m0 = blockIdx.y * 128, n0 = blockIdx.x * 128;
    const int NC = K >> 6;

    const int lrow = tid >> 1;
    const int lc0 = (tid & 1) * 4;
    const __nv_bfloat16* pAh = Ah + (size_t)(m0 + lrow) * K + lc0 * 8;
    const __nv_bfloat16* pAl = Al + (size_t)(m0 + lrow) * K + lc0 * 8;
    const __nv_bfloat16* pBh = Bh + (size_t)(n0 + lrow) * K + lc0 * 8;
    const __nv_bfloat16* pBl = Bl + (size_t)(n0 + lrow) * K + lc0 * 8;
    uint32_t soff[4];
#pragma unroll
    for (int i = 0; i < 4; ++i) {
        uint32_t b = lrow * 128 + (lc0 + i) * 16;
        soff[i] = b ^ ((b >> 3) & 0x70);
    }

#define LOAD_STAGE(st, c)                                                   \
    do {                                                                    \
        uint32_t base = sb + (uint32_t)(st) * STAGE_B;                      \
        size_t g = (size_t)(c) * 64;                                        \
        _Pragma("unroll") for (int i = 0; i < 4; ++i) {                     \
            cpa16(base + soff[i], pAh + g + i * 8);                         \
            cpa16(base + TILE_B + soff[i], pAl + g + i * 8);                \
            cpa16(base + 2 * TILE_B + soff[i], pBh + g + i * 8);            \
            cpa16(base + 3 * TILE_B + soff[i], pBl + g + i * 8);            \
        }                                                                   \
    } while (0)

    const int rowA = lid & 15, khA = lid >> 4;
    const int rowB = (lid & 7) | (((lid >> 4) & 1) << 3), khB = (lid >> 3) & 1;
    const uint32_t rbA = (uint32_t)(((wid & 1) * 64 + rowA) * 128);
    const uint32_t rbB = (uint32_t)(((wid >> 1) * 32 + rowB) * 128);
    const uint32_t xrA = (uint32_t)((rowA & 7) << 4);
    const uint32_t xrB = (uint32_t)((rowB & 7) << 4);
    uint32_t offA[4], offB[4];
#pragma unroll
    for (int ks = 0; ks < 4; ++ks) {
        offA[ks] = (uint32_t)(ks * 32 + khA * 16) ^ xrA;
        offB[ks] = (uint32_t)(ks * 32 + khB * 16) ^ xrB;
    }

    float acc[4][4][4];
#pragma unroll
    for (int i = 0; i < 4; ++i)
#pragma unroll
        for (int j = 0; j < 4; ++j)
#pragma unroll
            for (int r = 0; r < 4; ++r) acc[i][j][r] = 0.f;

    LOAD_STAGE(0, 0);
    cpa_commit();
    LOAD_STAGE(1, 1);
    cpa_commit();

    for (int c = 0; c < NC; ++c) {
        const int st = c % NS;
        cpa_wait1();
        __syncthreads();
        if (c + 2 < NC) LOAD_STAGE((c + 2) % NS, c + 2);
        cpa_commit();

        const uint32_t base = sb + (uint32_t)st * STAGE_B;
        const uint32_t aH = base + rbA;
        const uint32_t aL = base + TILE_B + rbA;
        const uint32_t bH = base + 2 * TILE_B + rbB;
        const uint32_t bL = base + 3 * TILE_B + rbB;

#pragma unroll
        for (int ks = 0; ks < 4; ++ks) {
            uint32_t fah[4][4], fal[4][4];
#pragma unroll
            for (int mi = 0; mi < 4; ++mi) {
                ldsm4(fah[mi], aH + mi * 2048 + offA[ks]);
                ldsm4(fal[mi], aL + mi * 2048 + offA[ks]);
            }
            uint32_t fbh[2][4], fbl[2][4];
#pragma unroll
            for (int p = 0; p < 2; ++p) {
                ldsm4(fbh[p], bH + p * 2048 + offB[ks]);
                ldsm4(fbl[p], bL + p * 2048 + offB[ks]);
            }
#pragma unroll
            for (int mi = 0; mi < 4; ++mi) {
#pragma unroll
                for (int ni = 0; ni < 4; ++ni) {
                    const int p = ni >> 1, hf = (ni & 1) * 2;
                    mma16816(acc[mi][ni], fah[mi], &fbh[p][hf]);
                    mma16816(acc[mi][ni], fah[mi], &fbl[p][hf]);
                    mma16816(acc[mi][ni], fal[mi], &fbh[p][hf]);
                }
            }
        }
    }

    const int q = lid >> 2, l = lid & 3;
    const int wm0 = m0 + (wid & 1) * 64;
    const int wn0 = n0 + (wid >> 1) * 32;
#pragma unroll
    for (int mi = 0; mi < 4; ++mi) {
#pragma unroll
        for (int ni = 0; ni < 4; ++ni) {
            const int r0 = wm0 + mi * 16 + q;
            const int cc = wn0 + ni * 8 + 2 * l;
            float2 v0 = make_float2(acc[mi][ni][0], acc[mi][ni][1]);
            float2 v1 = make_float2(acc[mi][ni][2], acc[mi][ni][3]);
            if (addend) {
                const float2 a0 =
                    *reinterpret_cast<const float2*>(addend + (size_t)r0 * N + cc);
                const float2 a1 = *reinterpret_cast<const float2*>(
                    addend + (size_t)(r0 + 8) * N + cc);
                v0.x += a0.x; v0.y += a0.y;
                v1.x += a1.x; v1.y += a1.y;
            }
            *reinterpret_cast<float2*>(Cout + (size_t)r0 * N + cc) = v0;
            *reinterpret_cast<float2*>(Cout + (size_t)(r0 + 8) * N + cc) = v1;
        }
    }
}
#undef LOAD_STAGE

// ---------------------------------------------------------------------------
// Tensor-core causal attention. CTA = (q-block ib of 128 rows, head h).
// logit = (q.k)/sqrt(D) - k2/(2 sqrt(D)); flash online softmax; split-bf16.
// Each warp: 16 q-rows x full 128 cols. 8 warps = 128 rows.
// ---------------------------------------------------------------------------
__global__ __launch_bounds__(256, 1) void attn_mma(
    const __nv_bfloat16* __restrict__ qHp, const __nv_bfloat16* __restrict__ qLp,
    const __nv_bfloat16* __restrict__ kHp, const __nv_bfloat16* __restrict__ kLp,
    const __nv_bfloat16* __restrict__ vtHp, const __nv_bfloat16* __restrict__ vtLp,
    const float* __restrict__ k2p, float* __restrict__ ctx) {
    extern __shared__ __align__(1024) char smem[];
    const uint32_t sb = smem_u32(smem);
    const int h = blockIdx.y;
    const int ib = (int)gridDim.x - 1 - (int)blockIdx.x;  // heavy blocks first
    const int tid = threadIdx.x, wid = tid >> 5, lid = tid & 31;

    const uint32_t sQ = sb;                 // [QH d0][QH d1][QL d0][QL d1]
    const uint32_t sK = sb + 4 * TILE_B;    // [KH d0][KH d1][KL d0][KL d1]
    const uint32_t sV = sb + 8 * TILE_B;    // [VH j0][VH j1][VL j0][VL j1]
    float* biasF = reinterpret_cast<float*>(smem + 12 * TILE_B);

    // loader mapping
    const int lrow = tid >> 1;
    const int lc0 = (tid & 1) * 4;
    uint32_t soff[4];
#pragma unroll
    for (int i = 0; i < 4; ++i) {
        uint32_t b = lrow * 128 + (lc0 + i) * 16;
        soff[i] = b ^ ((b >> 3) & 0x70);
    }

    // Q load (resident)
    {
        const __nv_bfloat16* qh = qHp + (size_t)(ib * 128 + lrow) * C + h * D + lc0 * 8;
        const __nv_bfloat16* ql = qLp + (size_t)(ib * 128 + lrow) * C + h * D + lc0 * 8;
#pragma unroll
        for (int dh = 0; dh < 2; ++dh)
#pragma unroll
            for (int i = 0; i < 4; ++i) {
                cpa16(sQ + dh * TILE_B + soff[i], qh + dh * 64 + i * 8);
                cpa16(sQ + 2 * TILE_B + dh * TILE_B + soff[i], ql + dh * 64 + i * 8);
            }
        cpa_commit();
    }

    // fragment index precompute
    const int rowA = lid & 15, khA = lid >> 4;
    const int rowB = (lid & 7) | (((lid >> 4) & 1) << 3), khB = (lid >> 3) & 1;
    const uint32_t rbA = (uint32_t)((wid * 16 + rowA) * 128);
    const uint32_t xrA = (uint32_t)((rowA & 7) << 4);
    const uint32_t xrB = (uint32_t)((rowB & 7) << 4);
    uint32_t offA[4], offB[4];
#pragma unroll
    for (int ks = 0; ks < 4; ++ks) {
        offA[ks] = (uint32_t)(ks * 32 + khA * 16) ^ xrA;
        offB[ks] = (uint32_t)(ks * 32 + khB * 16) ^ xrB;
    }

    const int c0 = 2 * (lid & 3);
    const int rl0 = wid * 16 + (lid >> 2);  // local row (also +8)
    const float invS = 0.08838834764831845f;  // 1/sqrt(128)
    const float hInv = 0.5f * invS;

    float oacc[16][4];
#pragma unroll
    for (int t = 0; t < 16; ++t)
#pragma unroll
        for (int r = 0; r < 4; ++r) oacc[t][r] = 0.f;
    float m0 = -1e30f, m1 = -1e30f, l0 = 0.f, l1 = 0.f;

    const __nv_bfloat16* kh0 = kHp + (size_t)lrow * C + h * D + lc0 * 8;
    const __nv_bfloat16* kl0 = kLp + (size_t)lrow * C + h * D + lc0 * 8;
    const __nv_bfloat16* vh0 = vtHp + (size_t)(h * D + lrow) * S + lc0 * 8;
    const __nv_bfloat16* vl0 = vtLp + (size_t)(h * D + lrow) * S + lc0 * 8;

    for (int jb = 0; jb <= ib; ++jb) {
        if (jb) __syncthreads();  // all warps done reading prior K/V
        // load K (2 d-units x hi/lo), V^T (2 j-units x hi/lo)
        {
            const __nv_bfloat16* kh = kh0 + (size_t)jb * 128 * C;
            const __nv_bfloat16* kl = kl0 + (size_t)jb * 128 * C;
            const __nv_bfloat16* vh = vh0 + jb * 128;
            const __nv_bfloat16* vl = vl0 + jb * 128;
#pragma unroll
            for (int u = 0; u < 2; ++u)
#pragma unroll
                for (int i = 0; i < 4; ++i) {
                    cpa16(sK + u * TILE_B + soff[i], kh + u * 64 + i * 8);
                    cpa16(sK + (2 + u) * TILE_B + soff[i], kl + u * 64 + i * 8);
                    cpa16(sV + u * TILE_B + soff[i], vh + u * 64 + i * 8);
                    cpa16(sV + (2 + u) * TILE_B + soff[i], vl + u * 64 + i * 8);
                }
            cpa_commit();
        }
        if (tid < 128)
            biasF[tid] = -k2p[(size_t)h * S + jb * 128 + tid] * hInv;
        cpa_wait0();
        __syncthreads();

        // --- QK^T: logits ---
        float sacc[16][4];
#pragma unroll
        for (int t = 0; t < 16; ++t)
#pragma unroll
            for (int r = 0; r < 4; ++r) sacc[t][r] = 0.f;

#pragma unroll
        for (int ks = 0; ks < 8; ++ks) {
            const uint32_t qo = (uint32_t)(ks >> 2) * TILE_B + offA[ks & 3];
            uint32_t ah[4], al[4];
            ldsm4(ah, sQ + rbA + qo);
            ldsm4(al, sQ + 2 * TILE_B + rbA + qo);
            const uint32_t ko = (uint32_t)(ks >> 2) * TILE_B + offB[ks & 3];
#pragma unroll
            for (int g = 0; g < 8; ++g) {
                const uint32_t rb = (uint32_t)((g * 16 + rowB) * 128);
                uint32_t bh[4], bl[4];
                ldsm4(bh, sK + rb + ko);
                ldsm4(bl, sK + 2 * TILE_B + rb + ko);
                mma16816(sacc[2 * g], ah, &bh[0]);
                mma16816(sacc[2 * g], ah, &bl[0]);
                mma16816(sacc[2 * g], al, &bh[0]);
                mma16816(sacc[2 * g + 1], ah, &bh[2]);
                mma16816(sacc[2 * g + 1], ah, &bl[2]);
                mma16816(sacc[2 * g + 1], al, &bh[2]);
            }
        }

        // --- bias + causal mask + online softmax ---
        float rmax0 = -1e30f, rmax1 = -1e30f;
#pragma unroll
        for (int t = 0; t < 16; ++t) {
            const int jl = 8 * t + c0;
            const float b0 = biasF[jl], b1 = biasF[jl + 1];
            sacc[t][0] = fmaf(sacc[t][0], invS, b0);
            sacc[t][1] = fmaf(sacc[t][1], invS, b1);
            sacc[t][2] = fmaf(sacc[t][2], invS, b0);
            sacc[t][3] = fmaf(sacc[t][3], invS, b1);
            if (jb == ib) {
                if (jl > rl0) sacc[t][0] = -1e30f;
                if (jl + 1 > rl0) sacc[t][1] = -1e30f;
                if (jl > rl0 + 8) sacc[t][2] = -1e30f;
                if (jl + 1 > rl0 + 8) sacc[t][3] = -1e30f;
            }
            rmax0 = fmaxf(rmax0, fmaxf(sacc[t][0], sacc[t][1]));
            rmax1 = fmaxf(rmax1, fmaxf(sacc[t][2], sacc[t][3]));
        }
        rmax0 = fmaxf(rmax0, __shfl_xor_sync(0xffffffffu, rmax0, 1));
        rmax0 = fmaxf(rmax0, __shfl_xor_sync(0xffffffffu, rmax0, 2));
        rmax1 = fmaxf(rmax1, __shfl_xor_sync(0xffffffffu, rmax1, 1));
        rmax1 = fmaxf(rmax1, __shfl_xor_sync(0xffffffffu, rmax1, 2));
        const float mn0 = fmaxf(m0, rmax0), mn1 = fmaxf(m1, rmax1);
        const float sc0 = __expf(m0 - mn0), sc1 = __expf(m1 - mn1);
        m0 = mn0; m1 = mn1;

        float rs0 = 0.f, rs1 = 0.f;
#pragma unroll
        for (int t = 0; t < 16; ++t) {
            const float p0 = __expf(sacc[t][0] - mn0);
            const float p1 = __expf(sacc[t][1] - mn0);
            const float p2 = __expf(sacc[t][2] - mn1);
            const float p3 = __expf(sacc[t][3] - mn1);
            rs0 += p0 + p1; rs1 += p2 + p3;
            sacc[t][0] = p0; sacc[t][1] = p1; sacc[t][2] = p2; sacc[t][3] = p3;
            oacc[t][0] *= sc0; oacc[t][1] *= sc0;
            oacc[t][2] *= sc1; oacc[t][3] *= sc1;
        }
        rs0 += __shfl_xor_sync(0xffffffffu, rs0, 1);
        rs0 += __shfl_xor_sync(0xffffffffu, rs0, 2);
        rs1 += __shfl_xor_sync(0xffffffffu, rs1, 1);
        rs1 += __shfl_xor_sync(0xffffffffu, rs1, 2);
        l0 = l0 * sc0 + rs0;
        l1 = l1 * sc1 + rs1;

        // --- P @ V ---
#pragma unroll
        for (int ks = 0; ks < 8; ++ks) {
            uint32_t aph[4], apl[4];
#pragma unroll
            for (int half = 0; half < 2; ++half) {
                const int t = 2 * ks + half;
                const float x0 = sacc[t][0], x1 = sacc[t][1];
                const float x2 = sacc[t][2], x3 = sacc[t][3];
                const uint32_t h01 = pack_bf2(x0, x1), h23 = pack_bf2(x2, x3);
                aph[half * 2 + 0] = h01;
                aph[half * 2 + 1] = h23;
                __nv_bfloat162 hb01 = *reinterpret_cast<const __nv_bfloat162*>(&h01);
                __nv_bfloat162 hb23 = *reinterpret_cast<const __nv_bfloat162*>(&h23);
                apl[half * 2 + 0] =
                    pack_bf2(x0 - __bfloat162float(hb01.x), x1 - __bfloat162float(hb01.y));
                apl[half * 2 + 1] =
                    pack_bf2(x2 - __bfloat162float(hb23.x), x3 - __bfloat162float(hb23.y));
            }
            const uint32_t vo = (uint32_t)(ks >> 2) * TILE_B + offB[ks & 3];
#pragma unroll
            for (int g = 0; g < 8; ++g) {
                const uint32_t rb = (uint32_t)((g * 16 + rowB) * 128);
                uint32_t vh[4], vl[4];
                ldsm4(vh, sV + rb + vo);
                ldsm4(vl, sV + 2 * TILE_B + rb + vo);
                mma16816(oacc[2 * g], aph, &vh[0]);
                mma16816(oacc[2 * g], aph, &vl[0]);
                mma16816(oacc[2 * g], apl, &vh[0]);
                mma16816(oacc[2 * g + 1], aph, &vh[2]);
                mma16816(oacc[2 * g + 1], aph, &vl[2]);
                mma16816(oacc[2 * g + 1], apl, &vh[2]);
            }
        }
    }

    // epilogue
    const float il0 = 1.f / l0, il1 = 1.f / l1;
    const int row0 = ib * 128 + rl0;
#pragma unroll
    for (int t = 0; t < 16; ++t) {
        const int col = h * D + 8 * t + c0;
        *reinterpret_cast<float2*>(ctx + (size_t)row0 * C + col) =
            make_float2(oacc[t][0] * il0, oacc[t][1] * il0);
        *reinterpret_cast<float2*>(ctx + (size_t)(row0 + 8) * C + col) =
            make_float2(oacc[t][2] * il1, oacc[t][3] * il1);
    }
}

// ---------------------------------------------------------------------------
// fp32 -> (bf16 hi, bf16 lo) split helpers
// ---------------------------------------------------------------------------
__device__ __forceinline__ void split1(float v, __nv_bfloat16& h, __nv_bfloat16& l) {
    h = __float2bfloat16(v);
    l = __float2bfloat16(v - __bfloat162float(h));
}

__global__ void split_kernel(const float* __restrict__ x,
                             __nv_bfloat16* __restrict__ oh,
                             __nv_bfloat16* __restrict__ ol, int n) {
    int i = blockIdx.x * blockDim.x + threadIdx.x;
    if (i < n) split1(x[i], oh[i], ol[i]);
}

__global__ void rmsnorm_split(const float* __restrict__ x,
                              const float* __restrict__ w,
                              __nv_bfloat16* __restrict__ oh,
                              __nv_bfloat16* __restrict__ ol) {
    const int row = blockIdx.x;
    const float* xr = x + (size_t)row * C;
    float s = 0.f;
    for (int c = threadIdx.x; c < C; c += blockDim.x) {
        float v = xr[c];
        s += v * v;
    }
#pragma unroll
    for (int off = 16; off; off >>= 1) s += __shfl_xor_sync(0xffffffffu, s, off);
    __shared__ float sh[8];
    if ((threadIdx.x & 31) == 0) sh[threadIdx.x >> 5] = s;
    __syncthreads();
    __shared__ float inv_s;
    if (threadIdx.x == 0) {
        float t = 0.f;
#pragma unroll
        for (int i = 0; i < 8; ++i) t += sh[i];
        inv_s = rsqrtf(t * (1.0f / C) + EPS);
    }
    __syncthreads();
    const float inv = inv_s;
    for (int c = threadIdx.x; c < C; c += blockDim.x) {
        float v = xr[c] * inv * w[c];
        split1(v, oh[(size_t)row * C + c], ol[(size_t)row * C + c]);
    }
}

__global__ void silu_mul_split(const float* __restrict__ gate,
                               const float* __restrict__ up,
                               __nv_bfloat16* __restrict__ oh,
                               __nv_bfloat16* __restrict__ ol, int n) {
    int i = blockIdx.x * blockDim.x + threadIdx.x;
    if (i < n) {
        float g = gate[i];
        float v = g / (1.f + __expf(-g)) * up[i];
        split1(v, oh[i], ol[i]);
    }
}

// ---------------------------------------------------------------------------
// RoPE -> split bf16 (+ optional ||k||^2)
// ---------------------------------------------------------------------------
__global__ void rope_split(const float* __restrict__ x,
                           const float* __restrict__ cosb,
                           const float* __restrict__ sinb,
                           __nv_bfloat16* __restrict__ oh,
                           __nv_bfloat16* __restrict__ ol,
                           float* __restrict__ k2out) {
    const int s = blockIdx.x, h = blockIdx.y, t = threadIdx.x;
    const float* row = x + (size_t)s * C + h * D;
    const float x1 = row[t], x2 = row[t + 64];
    const float o1 = x1 * cosb[s * D + t] - x2 * sinb[s * D + t];
    const float o2 = x2 * cosb[s * D + t + 64] + x1 * sinb[s * D + t + 64];
    const size_t base = (size_t)s * C + h * D;
    split1(o1, oh[base + t], ol[base + t]);
    split1(o2, oh[base + t + 64], ol[base + t + 64]);
    if (k2out) {
        float ss = o1 * o1 + o2 * o2;
#pragma unroll
        for (int off = 16; off; off >>= 1) ss += __shfl_xor_sync(0xffffffffu, ss, off);
        __shared__ float sh[2];
        if ((t & 31) == 0) sh[t >> 5] = ss;
        __syncthreads();
        if (t == 0) k2out[(size_t)h * S + s] = sh[0] + sh[1];
    }
}

// ---------------------------------------------------------------------------
// V transpose + split: v[S][C] -> vt[C][S] (bf16 hi/lo)
// ---------------------------------------------------------------------------
__global__ void vt_split(const float* __restrict__ v,
                         __nv_bfloat16* __restrict__ oth,
                         __nv_bfloat16* __restrict__ otl) {
    __shared__ float tile[32][33];
    const int cB = blockIdx.x * 32, sB = blockIdx.y * 32;
    for (int r = threadIdx.y; r < 32; r += 8)
        tile[r][threadIdx.x] = v[(size_t)(sB + r) * C + cB + threadIdx.x];
    __syncthreads();
    for (int r = threadIdx.y; r < 32; r += 8) {
        const float val = tile[threadIdx.x][r];  // v[sB+tx][cB+r]
        __nv_bfloat16 h, l;
        split1(val, h, l);
        oth[(size_t)(cB + r) * S + sB + threadIdx.x] = h;
        otl[(size_t)(cB + r) * S + sB + threadIdx.x] = l;
    }
}

// ---------------------------------------------------------------------------
// launch
// ---------------------------------------------------------------------------
static inline float* sym(const void* s) {
    void* p = nullptr;
    cudaGetSymbolAddress(&p, s);
    return (float*)p;
}

extern "C" void kernel_launch(void* const* d_in, const int* in_sizes, int n_in,
                              void* d_out, int out_size) {
    const float* hidden = (const float*)d_in[0];
    const float* cosb = (const float*)d_in[1];
    const float* sinb = (const float*)d_in[2];
    // d_in[3] attention_mask: exactly causal, handled analytically
    const float* ln1_w = (const float*)d_in[4];
    const float* wq = (const float*)d_in[5];
    const float* wk = (const float*)d_in[6];
    const float* wv = (const float*)d_in[7];
    const float* wo = (const float*)d_in[8];
    const float* ln2_w = (const float*)d_in[9];
    const float* wg = (const float*)d_in[10];
    const float* wu = (const float*)d_in[11];
    const float* wd = (const float*)d_in[12];
    float* out = (float*)d_out;

    cudaFuncSetAttribute(gemm_split, cudaFuncAttributeMaxDynamicSharedMemorySize,
                         GSMEM);
    cudaFuncSetAttribute(attn_mma, cudaFuncAttributeMaxDynamicSharedMemorySize,
                         ASMEM);

    float* q = sym(&g_q);
    float* k = sym(&g_k);
    float* v = sym(&g_v);
    float* ctx = sym(&g_ctx);
    float* hb = sym(&g_h);
    float* gate = sym(&g_gate);
    float* up = sym(&g_up);
    float* k2 = sym(&g_k2);
    __nv_bfloat16* qH = (__nv_bfloat16*)sym(&g_qH);
    __nv_bfloat16* qL = (__nv_bfloat16*)sym(&g_qL);
    __nv_bfloat16* kH = (__nv_bfloat16*)sym(&g_kH);
    __nv_bfloat16* kL = (__nv_bfloat16*)sym(&g_kL);
    __nv_bfloat16* vtH = (__nv_bfloat16*)sym(&g_vtH);
    __nv_bfloat16* vtL = (__nv_bfloat16*)sym(&g_vtL);
    __nv_bfloat16* xnH = (__nv_bfloat16*)sym(&g_xnH);
    __nv_bfloat16* xnL = (__nv_bfloat16*)sym(&g_xnL);
    __nv_bfloat16* yH = (__nv_bfloat16*)sym(&g_yH);
    __nv_bfloat16* yL = (__nv_bfloat16*)sym(&g_yL);
    __nv_bfloat16* cH = (__nv_bfloat16*)sym(&g_cH);
    __nv_bfloat16* cL = (__nv_bfloat16*)sym(&g_cL);
    __nv_bfloat16* aH = (__nv_bfloat16*)sym(&g_aH);
    __nv_bfloat16* aL = (__nv_bfloat16*)sym(&g_aL);
    __nv_bfloat16* wqH = (__nv_bfloat16*)sym(&g_wqH);
    __nv_bfloat16* wqL = (__nv_bfloat16*)sym(&g_wqL);
    __nv_bfloat16* wkH = (__nv_bfloat16*)sym(&g_wkH);
    __nv_bfloat16* wkL = (__nv_bfloat16*)sym(&g_wkL);
    __nv_bfloat16* wvH = (__nv_bfloat16*)sym(&g_wvH);
    __nv_bfloat16* wvL = (__nv_bfloat16*)sym(&g_wvL);
    __nv_bfloat16* woH = (__nv_bfloat16*)sym(&g_woH);
    __nv_bfloat16* woL = (__nv_bfloat16*)sym(&g_woL);
    __nv_bfloat16* wgH = (__nv_bfloat16*)sym(&g_wgH);
    __nv_bfloat16* wgL = (__nv_bfloat16*)sym(&g_wgL);
    __nv_bfloat16* wuH = (__nv_bfloat16*)sym(&g_wuH);
    __nv_bfloat16* wuL = (__nv_bfloat16*)sym(&g_wuL);
    __nv_bfloat16* wdH = (__nv_bfloat16*)sym(&g_wdH);
    __nv_bfloat16* wdL = (__nv_bfloat16*)sym(&g_wdL);

    const int TPB = 256;
    // weight splits
    split_kernel<<<(C * C + TPB - 1) / TPB, TPB>>>(wq, wqH, wqL, C * C);
    split_kernel<<<(C * C + TPB - 1) / TPB, TPB>>>(wk, wkH, wkL, C * C);
    split_kernel<<<(C * C + TPB - 1) / TPB, TPB>>>(wv, wvH, wvL, C * C);
    split_kernel<<<(C * C + TPB - 1) / TPB, TPB>>>(wo, woH, woL, C * C);
    split_kernel<<<(FF * C + TPB - 1) / TPB, TPB>>>(wg, wgH, wgL, FF * C);
    split_kernel<<<(FF * C + TPB - 1) / TPB, TPB>>>(wu, wuH, wuL, FF * C);
    split_kernel<<<(C * FF + TPB - 1) / TPB, TPB>>>(wd, wdH, wdL, C * FF);

    // 1. input RMSNorm (split output)
    rmsnorm_split<<<S, 256>>>(hidden, ln1_w, xnH, xnL);

    // 2. QKV projections (tensor-core split-bf16)
    dim3 gqkv(C / 128, S / 128);
    gemm_split<<<gqkv, 256, GSMEM>>>(xnH, xnL, wqH, wqL, q, nullptr, S, C, C);
    gemm_split<<<gqkv, 256, GSMEM>>>(xnH, xnL, wkH, wkL, k, nullptr, S, C, C);
    gemm_split<<<gqkv, 256, GSMEM>>>(xnH, xnL, wvH, wvL, v, nullptr, S, C, C);

    // 3. RoPE -> split bf16; V -> transposed split bf16
    dim3 grope(S, H);
    rope_split<<<grope, 64>>>(q, cosb, sinb, qH, qL, nullptr);
    rope_split<<<grope, 64>>>(k, cosb, sinb, kH, kL, k2);
    dim3 gvt(C / 32, S / 32);
    vt_split<<<gvt, dim3(32, 8)>>>(v, vtH, vtL);

    // 4. tensor-core flash attention
    dim3 gattn(S / 128, H);
    attn_mma<<<gattn, 256, ASMEM>>>(qH, qL, kH, kL, vtH, vtL, k2, ctx);

    // 5. output projection + residual
    split_kernel<<<(S * C + TPB - 1) / TPB, TPB>>>(ctx, cH, cL, S * C);
    gemm_split<<<gqkv, 256, GSMEM>>>(cH, cL, woH, woL, hb, hidden, S, C, C);

    // 6. post-attn RMSNorm
    rmsnorm_split<<<S, 256>>>(hb, ln2_w, yH, yL);

    // 7. FFN gate & up
    dim3 gff(FF / 128, S / 128);
    gemm_split<<<gff, 256, GSMEM>>>(yH, yL, wgH, wgL, gate, nullptr, S, FF, C);
    gemm_split<<<gff, 256, GSMEM>>>(yH, yL, wuH, wuL, up, nullptr, S, FF, C);

    // 8. SiLU(gate)*up -> split
    silu_mul_split<<<(S * FF + TPB - 1) / TPB, TPB>>>(gate, up, aH, aL, S * FF);

    // 9. down projection + residual -> final output
    dim3 gdown(C / 128, S / 128);
    gemm_split<<<gdown, 256, GSMEM>>>(aH, aL, wdH, wdL, out, hb, S, C, FF);
}

// round 7
// speedup vs baseline: 3.6041x; 1.0083x over previous
#include <cuda_runtime.h>
#include <cuda_bf16.h>
#include <math.h>
#include <stdint.h>

#define S 2048
#define C 2048
#define H 16
#define D 128
#define FF 8192
#define EPS 1e-6f

// GEMM tiling: 128x128 CTA tile, BK=64 bf16 (128B rows), 3-stage cp.async pipe
#define NS 3
#define TILE_B 16384              // 128 rows x 128 bytes
#define STAGE_B (4 * TILE_B)      // Ah, Al, Bh, Bl
#define GSMEM (NS * STAGE_B)      // 196608 bytes

// Attention smem: Q(4 units) + K(4) + V(4) + bias
#define ASMEM (12 * TILE_B + 512)

// ---------------------------------------------------------------------------
// Static device scratch
// ---------------------------------------------------------------------------
__device__ float g_q[S * C], g_k[S * C], g_v[S * C];
__device__ float g_h[S * C];
__device__ float g_gate[S * FF], g_up[S * FF];
__device__ float g_k2[H * S];
__device__ __nv_bfloat16 g_qH[S * C], g_qL[S * C];
__device__ __nv_bfloat16 g_kH[S * C], g_kL[S * C];
__device__ __nv_bfloat16 g_vtH[C * S], g_vtL[C * S];
__device__ __nv_bfloat16 g_xnH[S * C], g_xnL[S * C];
__device__ __nv_bfloat16 g_yH[S * C], g_yL[S * C];
__device__ __nv_bfloat16 g_cH[S * C], g_cL[S * C];
__device__ __nv_bfloat16 g_aH[S * FF], g_aL[S * FF];
__device__ __nv_bfloat16 g_wqH[C * C], g_wqL[C * C];
__device__ __nv_bfloat16 g_wkH[C * C], g_wkL[C * C];
__device__ __nv_bfloat16 g_wvH[C * C], g_wvL[C * C];
__device__ __nv_bfloat16 g_woH[C * C], g_woL[C * C];
__device__ __nv_bfloat16 g_wgH[FF * C], g_wgL[FF * C];
__device__ __nv_bfloat16 g_wuH[FF * C], g_wuL[FF * C];
__device__ __nv_bfloat16 g_wdH[C * FF], g_wdL[C * FF];

// ---------------------------------------------------------------------------
// PTX helpers (baseline ISA only)
// ---------------------------------------------------------------------------
__device__ __forceinline__ uint32_t smem_u32(const void* p) {
    uint32_t a;
    asm("{ .reg .u64 t; cvta.to.shared.u64 t, %1; cvt.u32.u64 %0, t; }"
        : "=r"(a) : "l"(p));
    return a;
}
__device__ __forceinline__ void cpa16(uint32_t d, const void* s) {
    asm volatile("cp.async.cg.shared.global [%0], [%1], 16;"
                 :: "r"(d), "l"(s) : "memory");
}
__device__ __forceinline__ void cpa_commit() {
    asm volatile("cp.async.commit_group;" ::: "memory");
}
__device__ __forceinline__ void cpa_wait1() {
    asm volatile("cp.async.wait_group 1;" ::: "memory");
}
__device__ __forceinline__ void cpa_wait0() {
    asm volatile("cp.async.wait_group 0;" ::: "memory");
}
__device__ __forceinline__ void ldsm4(uint32_t* r, uint32_t addr) {
    asm volatile(
        "ldmatrix.sync.aligned.m8n8.x4.shared.b16 {%0,%1,%2,%3}, [%4];"
        : "=r"(r[0]), "=r"(r[1]), "=r"(r[2]), "=r"(r[3]) : "r"(addr));
}
__device__ __forceinline__ void mma16816(float* c, const uint32_t* a,
                                         const uint32_t* b) {
    asm volatile(
        "mma.sync.aligned.m16n8k16.row.col.f32.bf16.bf16.f32 "
        "{%0,%1,%2,%3}, {%4,%5,%6,%7}, {%8,%9}, {%0,%1,%2,%3};"
        : "+f"(c[0]), "+f"(c[1]), "+f"(c[2]), "+f"(c[3])
        : "r"(a[0]), "r"(a[1]), "r"(a[2]), "r"(a[3]), "r"(b[0]), "r"(b[1]));
}
__device__ __forceinline__ uint32_t pack_bf2(float x, float y) {
    __nv_bfloat162 t = __floats2bfloat162_rn(x, y);
    return *reinterpret_cast<uint32_t*>(&t);
}

// ---------------------------------------------------------------------------
// Shared GEMM machinery (macros so both kernels inline the same body)
// ---------------------------------------------------------------------------
#define GEMM_PRE()                                                           \
    extern __shared__ __align__(1024) char smem[];                           \
    const uint32_t sb = smem_u32(smem);                                      \
    const int tid = threadIdx.x;                                             \
    const int wid = tid >> 5, lid = tid & 31;                                \
    const int lrow = tid >> 1;                                               \
    const int lc0 = (tid & 1) * 4;                                           \
    uint32_t soff[4];                                                        \
    _Pragma("unroll") for (int i = 0; i < 4; ++i) {                          \
        uint32_t b = lrow * 128 + (lc0 + i) * 16;                            \
        soff[i] = b ^ ((b >> 3) & 0x70);                                     \
    }                                                                        \
    const int rowA = lid & 15, khA = lid >> 4;                               \
    const int rowB = (lid & 7) | (((lid >> 4) & 1) << 3);                    \
    const int khB = (lid >> 3) & 1;                                          \
    const uint32_t rbA = (uint32_t)(((wid & 1) * 64 + rowA) * 128);          \
    const uint32_t rbB = (uint32_t)(((wid >> 1) * 32 + rowB) * 128);         \
    const uint32_t xrA = (uint32_t)((rowA & 7) << 4);                        \
    const uint32_t xrB = (uint32_t)((rowB & 7) << 4);                        \
    uint32_t offA[4], offB[4];                                               \
    _Pragma("unroll") for (int ks = 0; ks < 4; ++ks) {                       \
        offA[ks] = (uint32_t)(ks * 32 + khA * 16) ^ xrA;                     \
        offB[ks] = (uint32_t)(ks * 32 + khB * 16) ^ xrB;                     \
    }                                                                        \
    float acc[4][4][4];                                                      \
    _Pragma("unroll") for (int i = 0; i < 4; ++i)                            \
        _Pragma("unroll") for (int j = 0; j < 4; ++j)                        \
            _Pragma("unroll") for (int r = 0; r < 4; ++r) acc[i][j][r] = 0.f;

#define LOAD_STAGE(st, c)                                                    \
    do {                                                                     \
        uint32_t base = sb + (uint32_t)(st) * STAGE_B;                       \
        size_t g = (size_t)(c) * 64;                                         \
        _Pragma("unroll") for (int i = 0; i < 4; ++i) {                      \
            cpa16(base + soff[i], pAh + g + i * 8);                          \
            cpa16(base + TILE_B + soff[i], pAl + g + i * 8);                 \
            cpa16(base + 2 * TILE_B + soff[i], pBh + g + i * 8);             \
            cpa16(base + 3 * TILE_B + soff[i], pBl + g + i * 8);             \
        }                                                                    \
    } while (0)

// Main loop body: variant-major MMA ordering (dep distance 16)
#define GEMM_MAIN(NC)                                                        \
    LOAD_STAGE(0, 0);                                                        \
    cpa_commit();                                                            \
    LOAD_STAGE(1, 1);                                                        \
    cpa_commit();                                                            \
    for (int c = 0; c < (NC); ++c) {                                         \
        const int st = c % NS;                                               \
        cpa_wait1();                                                         \
        __syncthreads();                                                     \
        if (c + 2 < (NC)) LOAD_STAGE((c + 2) % NS, c + 2);                   \
        cpa_commit();                                                        \
        const uint32_t base = sb + (uint32_t)st * STAGE_B;                   \
        const uint32_t aHa = base + rbA;                                     \
        const uint32_t aLa = base + TILE_B + rbA;                            \
        const uint32_t bHa = base + 2 * TILE_B + rbB;                        \
        const uint32_t bLa = base + 3 * TILE_B + rbB;                        \
        _Pragma("unroll") for (int ks = 0; ks < 4; ++ks) {                   \
            uint32_t fah[4][4], fal[4][4];                                   \
            _Pragma("unroll") for (int mi = 0; mi < 4; ++mi) {               \
                ldsm4(fah[mi], aHa + mi * 2048 + offA[ks]);                  \
                ldsm4(fal[mi], aLa + mi * 2048 + offA[ks]);                  \
            }                                                                \
            uint32_t fbh[2][4], fbl[2][4];                                   \
            _Pragma("unroll") for (int p = 0; p < 2; ++p) {                  \
                ldsm4(fbh[p], bHa + p * 2048 + offB[ks]);                    \
                ldsm4(fbl[p], bLa + p * 2048 + offB[ks]);                    \
            }                                                                \
            _Pragma("unroll") for (int mi = 0; mi < 4; ++mi)                 \
                _Pragma("unroll") for (int ni = 0; ni < 4; ++ni)             \
                    mma16816(acc[mi][ni], fah[mi], &fbh[ni >> 1][(ni & 1) * 2]); \
            _Pragma("unroll") for (int mi = 0; mi < 4; ++mi)                 \
                _Pragma("unroll") for (int ni = 0; ni < 4; ++ni)             \
                    mma16816(acc[mi][ni], fah[mi], &fbl[ni >> 1][(ni & 1) * 2]); \
            _Pragma("unroll") for (int mi = 0; mi < 4; ++mi)                 \
                _Pragma("unroll") for (int ni = 0; ni < 4; ++ni)             \
                    mma16816(acc[mi][ni], fal[mi], &fbh[ni >> 1][(ni & 1) * 2]); \
        }                                                                    \
    }

// ---------------------------------------------------------------------------
// gemm_split: single-B GEMM with fp32 addend (WO, down projections)
// ---------------------------------------------------------------------------
__global__ __launch_bounds__(256, 1) void gemm_split(
    const __nv_bfloat16* __restrict__ Ah, const __nv_bfloat16* __restrict__ Al,
    const __nv_bfloat16* __restrict__ Bh, const __nv_bfloat16* __restrict__ Bl,
    float* __restrict__ Cout, const float* __restrict__ addend,
    int M, int N, int K) {
    GEMM_PRE();
    const int m0 = blockIdx.y * 128, n0 = blockIdx.x * 128;
    const __nv_bfloat16* pAh = Ah + (size_t)(m0 + lrow) * K + lc0 * 8;
    const __nv_bfloat16* pAl = Al + (size_t)(m0 + lrow) * K + lc0 * 8;
    const __nv_bfloat16* pBh = Bh + (size_t)(n0 + lrow) * K + lc0 * 8;
    const __nv_bfloat16* pBl = Bl + (size_t)(n0 + lrow) * K + lc0 * 8;
    const int NC = K >> 6;
    GEMM_MAIN(NC);

    const int q = lid >> 2, l = lid & 3;
    const int wm0 = m0 + (wid & 1) * 64;
    const int wn0 = n0 + (wid >> 1) * 32;
#pragma unroll
    for (int mi = 0; mi < 4; ++mi) {
#pragma unroll
        for (int ni = 0; ni < 4; ++ni) {
            const int r0 = wm0 + mi * 16 + q;
            const int cc = wn0 + ni * 8 + 2 * l;
            float2 v0 = make_float2(acc[mi][ni][0], acc[mi][ni][1]);
            float2 v1 = make_float2(acc[mi][ni][2], acc[mi][ni][3]);
            if (addend) {
                const float2 a0 =
                    *reinterpret_cast<const float2*>(addend + (size_t)r0 * N + cc);
                const float2 a1 = *reinterpret_cast<const float2*>(
                    addend + (size_t)(r0 + 8) * N + cc);
                v0.x += a0.x; v0.y += a0.y;
                v1.x += a1.x; v1.y += a1.y;
            }
            *reinterpret_cast<float2*>(Cout + (size_t)r0 * N + cc) = v0;
            *reinterpret_cast<float2*>(Cout + (size_t)(r0 + 8) * N + cc) = v1;
        }
    }
}

// ---------------------------------------------------------------------------
// gemm_split3: fused multi-B GEMM (QKV in one launch; gate+up in one launch)
// blockIdx.x selects (B, C) set: sel = bx / nblk_per, n0 = (bx % nblk_per)*128
// ---------------------------------------------------------------------------
__global__ __launch_bounds__(256, 1) void gemm_split3(
    const __nv_bfloat16* __restrict__ Ah, const __nv_bfloat16* __restrict__ Al,
    const __nv_bfloat16* __restrict__ B0h, const __nv_bfloat16* __restrict__ B0l,
    float* __restrict__ C0,
    const __nv_bfloat16* __restrict__ B1h, const __nv_bfloat16* __restrict__ B1l,
    float* __restrict__ C1,
    const __nv_bfloat16* __restrict__ B2h, const __nv_bfloat16* __restrict__ B2l,
    float* __restrict__ C2,
    int M, int Nper, int K, int nblk_per) {
    GEMM_PRE();
    const int sel = blockIdx.x / nblk_per;
    const int n0 = (blockIdx.x % nblk_per) * 128;
    const int m0 = blockIdx.y * 128;
    const __nv_bfloat16* Bh = (sel == 0) ? B0h : (sel == 1) ? B1h : B2h;
    const __nv_bfloat16* Bl = (sel == 0) ? B0l : (sel == 1) ? B1l : B2l;
    float* Cout = (sel == 0) ? C0 : (sel == 1) ? C1 : C2;
    const __nv_bfloat16* pAh = Ah + (size_t)(m0 + lrow) * K + lc0 * 8;
    const __nv_bfloat16* pAl = Al + (size_t)(m0 + lrow) * K + lc0 * 8;
    const __nv_bfloat16* pBh = Bh + (size_t)(n0 + lrow) * K + lc0 * 8;
    const __nv_bfloat16* pBl = Bl + (size_t)(n0 + lrow) * K + lc0 * 8;
    const int NC = K >> 6;
    GEMM_MAIN(NC);

    const int q = lid >> 2, l = lid & 3;
    const int wm0 = m0 + (wid & 1) * 64;
    const int wn0 = n0 + (wid >> 1) * 32;
#pragma unroll
    for (int mi = 0; mi < 4; ++mi) {
#pragma unroll
        for (int ni = 0; ni < 4; ++ni) {
            const int r0 = wm0 + mi * 16 + q;
            const int cc = wn0 + ni * 8 + 2 * l;
            *reinterpret_cast<float2*>(Cout + (size_t)r0 * Nper + cc) =
                make_float2(acc[mi][ni][0], acc[mi][ni][1]);
            *reinterpret_cast<float2*>(Cout + (size_t)(r0 + 8) * Nper + cc) =
                make_float2(acc[mi][ni][2], acc[mi][ni][3]);
        }
    }
}

// ---------------------------------------------------------------------------
// Tensor-core causal attention. CTA = (q-block ib of 128 rows, head h).
// logit = (q.k)/sqrt(D) - k2/(2 sqrt(D)); flash online softmax; split-bf16.
// Writes ctx as split bf16 (hi/lo) directly.
// ---------------------------------------------------------------------------
__global__ __launch_bounds__(256, 1) void attn_mma(
    const __nv_bfloat16* __restrict__ qHp, const __nv_bfloat16* __restrict__ qLp,
    const __nv_bfloat16* __restrict__ kHp, const __nv_bfloat16* __restrict__ kLp,
    const __nv_bfloat16* __restrict__ vtHp, const __nv_bfloat16* __restrict__ vtLp,
    const float* __restrict__ k2p,
    __nv_bfloat16* __restrict__ ctxH, __nv_bfloat16* __restrict__ ctxL) {
    extern __shared__ __align__(1024) char smem[];
    const uint32_t sb = smem_u32(smem);
    const int h = blockIdx.y;
    const int ib = (int)gridDim.x - 1 - (int)blockIdx.x;  // heavy blocks first
    const int tid = threadIdx.x, wid = tid >> 5, lid = tid & 31;

    const uint32_t sQ = sb;
    const uint32_t sK = sb + 4 * TILE_B;
    const uint32_t sV = sb + 8 * TILE_B;
    float* biasF = reinterpret_cast<float*>(smem + 12 * TILE_B);

    const int lrow = tid >> 1;
    const int lc0 = (tid & 1) * 4;
    uint32_t soff[4];
#pragma unroll
    for (int i = 0; i < 4; ++i) {
        uint32_t b = lrow * 128 + (lc0 + i) * 16;
        soff[i] = b ^ ((b >> 3) & 0x70);
    }

    // Q load (resident)
    {
        const __nv_bfloat16* qh = qHp + (size_t)(ib * 128 + lrow) * C + h * D + lc0 * 8;
        const __nv_bfloat16* ql = qLp + (size_t)(ib * 128 + lrow) * C + h * D + lc0 * 8;
#pragma unroll
        for (int dh = 0; dh < 2; ++dh)
#pragma unroll
            for (int i = 0; i < 4; ++i) {
                cpa16(sQ + dh * TILE_B + soff[i], qh + dh * 64 + i * 8);
                cpa16(sQ + 2 * TILE_B + dh * TILE_B + soff[i], ql + dh * 64 + i * 8);
            }
        cpa_commit();
    }

    const int rowA = lid & 15, khA = lid >> 4;
    const int rowB = (lid & 7) | (((lid >> 4) & 1) << 3), khB = (lid >> 3) & 1;
    const uint32_t rbA = (uint32_t)((wid * 16 + rowA) * 128);
    const uint32_t xrA = (uint32_t)((rowA & 7) << 4);
    const uint32_t xrB = (uint32_t)((rowB & 7) << 4);
    uint32_t offA[4], offB[4];
#pragma unroll
    for (int ks = 0; ks < 4; ++ks) {
        offA[ks] = (uint32_t)(ks * 32 + khA * 16) ^ xrA;
        offB[ks] = (uint32_t)(ks * 32 + khB * 16) ^ xrB;
    }

    const int c0 = 2 * (lid & 3);
    const int rl0 = wid * 16 + (lid >> 2);
    const float invS = 0.08838834764831845f;  // 1/sqrt(128)
    const float hInv = 0.5f * invS;

    float oacc[16][4];
#pragma unroll
    for (int t = 0; t < 16; ++t)
#pragma unroll
        for (int r = 0; r < 4; ++r) oacc[t][r] = 0.f;
    float m0 = -1e30f, m1 = -1e30f, l0 = 0.f, l1 = 0.f;

    const __nv_bfloat16* kh0 = kHp + (size_t)lrow * C + h * D + lc0 * 8;
    const __nv_bfloat16* kl0 = kLp + (size_t)lrow * C + h * D + lc0 * 8;
    const __nv_bfloat16* vh0 = vtHp + (size_t)(h * D + lrow) * S + lc0 * 8;
    const __nv_bfloat16* vl0 = vtLp + (size_t)(h * D + lrow) * S + lc0 * 8;

    for (int jb = 0; jb <= ib; ++jb) {
        if (jb) __syncthreads();
        {
            const __nv_bfloat16* kh = kh0 + (size_t)jb * 128 * C;
            const __nv_bfloat16* kl = kl0 + (size_t)jb * 128 * C;
            const __nv_bfloat16* vh = vh0 + jb * 128;
            const __nv_bfloat16* vl = vl0 + jb * 128;
#pragma unroll
            for (int u = 0; u < 2; ++u)
#pragma unroll
                for (int i = 0; i < 4; ++i) {
                    cpa16(sK + u * TILE_B + soff[i], kh + u * 64 + i * 8);
                    cpa16(sK + (2 + u) * TILE_B + soff[i], kl + u * 64 + i * 8);
                    cpa16(sV + u * TILE_B + soff[i], vh + u * 64 + i * 8);
                    cpa16(sV + (2 + u) * TILE_B + soff[i], vl + u * 64 + i * 8);
                }
            cpa_commit();
        }
        if (tid < 128)
            biasF[tid] = -k2p[(size_t)h * S + jb * 128 + tid] * hInv;
        cpa_wait0();
        __syncthreads();

        // --- QK^T (variant-major over pairs of key tiles) ---
        float sacc[16][4];
#pragma unroll
        for (int t = 0; t < 16; ++t)
#pragma unroll
            for (int r = 0; r < 4; ++r) sacc[t][r] = 0.f;

#pragma unroll
        for (int ks = 0; ks < 8; ++ks) {
            const uint32_t qo = (uint32_t)(ks >> 2) * TILE_B + offA[ks & 3];
            uint32_t ah[4], al[4];
            ldsm4(ah, sQ + rbA + qo);
            ldsm4(al, sQ + 2 * TILE_B + rbA + qo);
            const uint32_t ko = (uint32_t)(ks >> 2) * TILE_B + offB[ks & 3];
#pragma unroll
            for (int g = 0; g < 8; g += 2) {
                const uint32_t r0 = (uint32_t)((g * 16 + rowB) * 128);
                const uint32_t r1 = (uint32_t)(((g + 1) * 16 + rowB) * 128);
                uint32_t bh0[4], bl0[4], bh1[4], bl1[4];
                ldsm4(bh0, sK + r0 + ko);
                ldsm4(bl0, sK + 2 * TILE_B + r0 + ko);
                ldsm4(bh1, sK + r1 + ko);
                ldsm4(bl1, sK + 2 * TILE_B + r1 + ko);
                // hh
                mma16816(sacc[2 * g + 0], ah, &bh0[0]);
                mma16816(sacc[2 * g + 1], ah, &bh0[2]);
                mma16816(sacc[2 * g + 2], ah, &bh1[0]);
                mma16816(sacc[2 * g + 3], ah, &bh1[2]);
                // hl
                mma16816(sacc[2 * g + 0], ah, &bl0[0]);
                mma16816(sacc[2 * g + 1], ah, &bl0[2]);
                mma16816(sacc[2 * g + 2], ah, &bl1[0]);
                mma16816(sacc[2 * g + 3], ah, &bl1[2]);
                // lh
                mma16816(sacc[2 * g + 0], al, &bh0[0]);
                mma16816(sacc[2 * g + 1], al, &bh0[2]);
                mma16816(sacc[2 * g + 2], al, &bh1[0]);
                mma16816(sacc[2 * g + 3], al, &bh1[2]);
            }
        }

        // --- bias + causal mask + online softmax ---
        float rmax0 = -1e30f, rmax1 = -1e30f;
#pragma unroll
        for (int t = 0; t < 16; ++t) {
            const int jl = 8 * t + c0;
            const float b0 = biasF[jl], b1 = biasF[jl + 1];
            sacc[t][0] = fmaf(sacc[t][0], invS, b0);
            sacc[t][1] = fmaf(sacc[t][1], invS, b1);
            sacc[t][2] = fmaf(sacc[t][2], invS, b0);
            sacc[t][3] = fmaf(sacc[t][3], invS, b1);
            if (jb == ib) {
                if (jl > rl0) sacc[t][0] = -1e30f;
                if (jl + 1 > rl0) sacc[t][1] = -1e30f;
                if (jl > rl0 + 8) sacc[t][2] = -1e30f;
                if (jl + 1 > rl0 + 8) sacc[t][3] = -1e30f;
            }
            rmax0 = fmaxf(rmax0, fmaxf(sacc[t][0], sacc[t][1]));
            rmax1 = fmaxf(rmax1, fmaxf(sacc[t][2], sacc[t][3]));
        }
        rmax0 = fmaxf(rmax0, __shfl_xor_sync(0xffffffffu, rmax0, 1));
        rmax0 = fmaxf(rmax0, __shfl_xor_sync(0xffffffffu, rmax0, 2));
        rmax1 = fmaxf(rmax1, __shfl_xor_sync(0xffffffffu, rmax1, 1));
        rmax1 = fmaxf(rmax1, __shfl_xor_sync(0xffffffffu, rmax1, 2));
        const float mn0 = fmaxf(m0, rmax0), mn1 = fmaxf(m1, rmax1);
        const float sc0 = __expf(m0 - mn0), sc1 = __expf(m1 - mn1);
        m0 = mn0; m1 = mn1;

        float rs0 = 0.f, rs1 = 0.f;
#pragma unroll
        for (int t = 0; t < 16; ++t) {
            const float p0 = __expf(sacc[t][0] - mn0);
            const float p1 = __expf(sacc[t][1] - mn0);
            const float p2 = __expf(sacc[t][2] - mn1);
            const float p3 = __expf(sacc[t][3] - mn1);
            rs0 += p0 + p1; rs1 += p2 + p3;
            sacc[t][0] = p0; sacc[t][1] = p1; sacc[t][2] = p2; sacc[t][3] = p3;
            oacc[t][0] *= sc0; oacc[t][1] *= sc0;
            oacc[t][2] *= sc1; oacc[t][3] *= sc1;
        }
        rs0 += __shfl_xor_sync(0xffffffffu, rs0, 1);
        rs0 += __shfl_xor_sync(0xffffffffu, rs0, 2);
        rs1 += __shfl_xor_sync(0xffffffffu, rs1, 1);
        rs1 += __shfl_xor_sync(0xffffffffu, rs1, 2);
        l0 = l0 * sc0 + rs0;
        l1 = l1 * sc1 + rs1;

        // --- P @ V (variant-major over pairs of value tiles) ---
#pragma unroll
        for (int ks = 0; ks < 8; ++ks) {
            uint32_t aph[4], apl[4];
#pragma unroll
            for (int half = 0; half < 2; ++half) {
                const int t = 2 * ks + half;
                const float x0 = sacc[t][0], x1 = sacc[t][1];
                const float x2 = sacc[t][2], x3 = sacc[t][3];
                const uint32_t h01 = pack_bf2(x0, x1), h23 = pack_bf2(x2, x3);
                aph[half * 2 + 0] = h01;
                aph[half * 2 + 1] = h23;
                __nv_bfloat162 hb01 = *reinterpret_cast<const __nv_bfloat162*>(&h01);
                __nv_bfloat162 hb23 = *reinterpret_cast<const __nv_bfloat162*>(&h23);
                apl[half * 2 + 0] =
                    pack_bf2(x0 - __bfloat162float(hb01.x), x1 - __bfloat162float(hb01.y));
                apl[half * 2 + 1] =
                    pack_bf2(x2 - __bfloat162float(hb23.x), x3 - __bfloat162float(hb23.y));
            }
            const uint32_t vo = (uint32_t)(ks >> 2) * TILE_B + offB[ks & 3];
#pragma unroll
            for (int g = 0; g < 8; g += 2) {
                const uint32_t r0 = (uint32_t)((g * 16 + rowB) * 128);
                const uint32_t r1 = (uint32_t)(((g + 1) * 16 + rowB) * 128);
                uint32_t vh0[4], vl0[4], vh1[4], vl1[4];
                ldsm4(vh0, sV + r0 + vo);
                ldsm4(vl0, sV + 2 * TILE_B + r0 + vo);
                ldsm4(vh1, sV + r1 + vo);
                ldsm4(vl1, sV + 2 * TILE_B + r1 + vo);
                // hh
                mma16816(oacc[2 * g + 0], aph, &vh0[0]);
                mma16816(oacc[2 * g + 1], aph, &vh0[2]);
                mma16816(oacc[2 * g + 2], aph, &vh1[0]);
                mma16816(oacc[2 * g + 3], aph, &vh1[2]);
                // hl
                mma16816(oacc[2 * g + 0], aph, &vl0[0]);
                mma16816(oacc[2 * g + 1], aph, &vl0[2]);
                mma16816(oacc[2 * g + 2], aph, &vl1[0]);
                mma16816(oacc[2 * g + 3], aph, &vl1[2]);
                // lh
                mma16816(oacc[2 * g + 0], apl, &vh0[0]);
                mma16816(oacc[2 * g + 1], apl, &vh0[2]);
                mma16816(oacc[2 * g + 2], apl, &vh1[0]);
                mma16816(oacc[2 * g + 3], apl, &vh1[2]);
            }
        }
    }

    // epilogue: normalized split-bf16 ctx
    const float il0 = 1.f / l0, il1 = 1.f / l1;
    const int row0 = ib * 128 + rl0;
#pragma unroll
    for (int t = 0; t < 16; ++t) {
        const int col = h * D + 8 * t + c0;
        const float x0 = oacc[t][0] * il0, x1 = oacc[t][1] * il0;
        const float x2 = oacc[t][2] * il1, x3 = oacc[t][3] * il1;
        const uint32_t h01 = pack_bf2(x0, x1), h23 = pack_bf2(x2, x3);
        __nv_bfloat162 hb01 = *reinterpret_cast<const __nv_bfloat162*>(&h01);
        __nv_bfloat162 hb23 = *reinterpret_cast<const __nv_bfloat162*>(&h23);
        const uint32_t l01 =
            pack_bf2(x0 - __bfloat162float(hb01.x), x1 - __bfloat162float(hb01.y));
        const uint32_t l23 =
            pack_bf2(x2 - __bfloat162float(hb23.x), x3 - __bfloat162float(hb23.y));
        *reinterpret_cast<uint32_t*>(&ctxH[(size_t)row0 * C + col]) = h01;
        *reinterpret_cast<uint32_t*>(&ctxL[(size_t)row0 * C + col]) = l01;
        *reinterpret_cast<uint32_t*>(&ctxH[(size_t)(row0 + 8) * C + col]) = h23;
        *reinterpret_cast<uint32_t*>(&ctxL[(size_t)(row0 + 8) * C + col]) = l23;
    }
}

// ---------------------------------------------------------------------------
// fp32 -> (bf16 hi, bf16 lo) split helpers
// ---------------------------------------------------------------------------
__device__ __forceinline__ void split1(float v, __nv_bfloat16& h, __nv_bfloat16& l) {
    h = __float2bfloat16(v);
    l = __float2bfloat16(v - __bfloat162float(h));
}

__global__ void split_kernel(const float* __restrict__ x,
                             __nv_bfloat16* __restrict__ oh,
                             __nv_bfloat16* __restrict__ ol, int n) {
    int i = blockIdx.x * blockDim.x + threadIdx.x;
    if (i < n) split1(x[i], oh[i], ol[i]);
}

__global__ void rmsnorm_split(const float* __restrict__ x,
                              const float* __restrict__ w,
                              __nv_bfloat16* __restrict__ oh,
                              __nv_bfloat16* __restrict__ ol) {
    const int row = blockIdx.x;
    const float* xr = x + (size_t)row * C;
    float s = 0.f;
    for (int c = threadIdx.x; c < C; c += blockDim.x) {
        float v = xr[c];
        s += v * v;
    }
#pragma unroll
    for (int off = 16; off; off >>= 1) s += __shfl_xor_sync(0xffffffffu, s, off);
    __shared__ float sh[8];
    if ((threadIdx.x & 31) == 0) sh[threadIdx.x >> 5] = s;
    __syncthreads();
    __shared__ float inv_s;
    if (threadIdx.x == 0) {
        float t = 0.f;
#pragma unroll
        for (int i = 0; i < 8; ++i) t += sh[i];
        inv_s = rsqrtf(t * (1.0f / C) + EPS);
    }
    __syncthreads();
    const float inv = inv_s;
    for (int c = threadIdx.x; c < C; c += blockDim.x) {
        float v = xr[c] * inv * w[c];
        split1(v, oh[(size_t)row * C + c], ol[(size_t)row * C + c]);
    }
}

__global__ void silu_mul_split(const float* __restrict__ gate,
                               const float* __restrict__ up,
                               __nv_bfloat16* __restrict__ oh,
                               __nv_bfloat16* __restrict__ ol, int n) {
    int i = blockIdx.x * blockDim.x + threadIdx.x;
    if (i < n) {
        float g = gate[i];
        float v = g / (1.f + __expf(-g)) * up[i];
        split1(v, oh[i], ol[i]);
    }
}

// ---------------------------------------------------------------------------
// RoPE -> split bf16 (+ optional ||k||^2)
// ---------------------------------------------------------------------------
__global__ void rope_split(const float* __restrict__ x,
                           const float* __restrict__ cosb,
                           const float* __restrict__ sinb,
                           __nv_bfloat16* __restrict__ oh,
                           __nv_bfloat16* __restrict__ ol,
                           float* __restrict__ k2out) {
    const int s = blockIdx.x, h = blockIdx.y, t = threadIdx.x;
    const float* row = x + (size_t)s * C + h * D;
    const float x1 = row[t], x2 = row[t + 64];
    const float o1 = x1 * cosb[s * D + t] - x2 * sinb[s * D + t];
    const float o2 = x2 * cosb[s * D + t + 64] + x1 * sinb[s * D + t + 64];
    const size_t base = (size_t)s * C + h * D;
    split1(o1, oh[base + t], ol[base + t]);
    split1(o2, oh[base + t + 64], ol[base + t + 64]);
    if (k2out) {
        float ss = o1 * o1 + o2 * o2;
#pragma unroll
        for (int off = 16; off; off >>= 1) ss += __shfl_xor_sync(0xffffffffu, ss, off);
        __shared__ float sh[2];
        if ((t & 31) == 0) sh[t >> 5] = ss;
        __syncthreads();
        if (t == 0) k2out[(size_t)h * S + s] = sh[0] + sh[1];
    }
}

// ---------------------------------------------------------------------------
// V transpose + split: v[S][C] -> vt[C][S] (bf16 hi/lo)
// ---------------------------------------------------------------------------
__global__ void vt_split(const float* __restrict__ v,
                         __nv_bfloat16* __restrict__ oth,
                         __nv_bfloat16* __restrict__ otl) {
    __shared__ float tile[32][33];
    const int cB = blockIdx.x * 32, sB = blockIdx.y * 32;
    for (int r = threadIdx.y; r < 32; r += 8)
        tile[r][threadIdx.x] = v[(size_t)(sB + r) * C + cB + threadIdx.x];
    __syncthreads();
    for (int r = threadIdx.y; r < 32; r += 8) {
        const float val = tile[threadIdx.x][r];
        __nv_bfloat16 h, l;
        split1(val, h, l);
        oth[(size_t)(cB + r) * S + sB + threadIdx.x] = h;
        otl[(size_t)(cB + r) * S + sB + threadIdx.x] = l;
    }
}

// ---------------------------------------------------------------------------
// launch
// ---------------------------------------------------------------------------
static inline float* sym(const void* s) {
    void* p = nullptr;
    cudaGetSymbolAddress(&p, s);
    return (float*)p;
}

extern "C" void kernel_launch(void* const* d_in, const int* in_sizes, int n_in,
                              void* d_out, int out_size) {
    const float* hidden = (const float*)d_in[0];
    const float* cosb = (const float*)d_in[1];
    const float* sinb = (const float*)d_in[2];
    // d_in[3] attention_mask: exactly causal, handled analytically
    const float* ln1_w = (const float*)d_in[4];
    const float* wq = (const float*)d_in[5];
    const float* wk = (const float*)d_in[6];
    const float* wv = (const float*)d_in[7];
    const float* wo = (const float*)d_in[8];
    const float* ln2_w = (const float*)d_in[9];
    const float* wg = (const float*)d_in[10];
    const float* wu = (const float*)d_in[11];
    const float* wd = (const float*)d_in[12];
    float* out = (float*)d_out;

    cudaFuncSetAttribute(gemm_split, cudaFuncAttributeMaxDynamicSharedMemorySize,
                         GSMEM);
    cudaFuncSetAttribute(gemm_split3, cudaFuncAttributeMaxDynamicSharedMemorySize,
                         GSMEM);
    cudaFuncSetAttribute(attn_mma, cudaFuncAttributeMaxDynamicSharedMemorySize,
                         ASMEM);

    float* q = sym(&g_q);
    float* k = sym(&g_k);
    float* v = sym(&g_v);
    float* hb = sym(&g_h);
    float* gate = sym(&g_gate);
    float* up = sym(&g_up);
    float* k2 = sym(&g_k2);
    __nv_bfloat16* qH = (__nv_bfloat16*)sym(&g_qH);
    __nv_bfloat16* qL = (__nv_bfloat16*)sym(&g_qL);
    __nv_bfloat16* kH = (__nv_bfloat16*)sym(&g_kH);
    __nv_bfloat16* kL = (__nv_bfloat16*)sym(&g_kL);
    __nv_bfloat16* vtH = (__nv_bfloat16*)sym(&g_vtH);
    __nv_bfloat16* vtL = (__nv_bfloat16*)sym(&g_vtL);
    __nv_bfloat16* xnH = (__nv_bfloat16*)sym(&g_xnH);
    __nv_bfloat16* xnL = (__nv_bfloat16*)sym(&g_xnL);
    __nv_bfloat16* yH = (__nv_bfloat16*)sym(&g_yH);
    __nv_bfloat16* yL = (__nv_bfloat16*)sym(&g_yL);
    __nv_bfloat16* cH = (__nv_bfloat16*)sym(&g_cH);
    __nv_bfloat16* cL = (__nv_bfloat16*)sym(&g_cL);
    __nv_bfloat16* aH = (__nv_bfloat16*)sym(&g_aH);
    __nv_bfloat16* aL = (__nv_bfloat16*)sym(&g_aL);
    __nv_bfloat16* wqH = (__nv_bfloat16*)sym(&g_wqH);
    __nv_bfloat16* wqL = (__nv_bfloat16*)sym(&g_wqL);
    __nv_bfloat16* wkH = (__nv_bfloat16*)sym(&g_wkH);
    __nv_bfloat16* wkL = (__nv_bfloat16*)sym(&g_wkL);
    __nv_bfloat16* wvH = (__nv_bfloat16*)sym(&g_wvH);
    __nv_bfloat16* wvL = (__nv_bfloat16*)sym(&g_wvL);
    __nv_bfloat16* woH = (__nv_bfloat16*)sym(&g_woH);
    __nv_bfloat16* woL = (__nv_bfloat16*)sym(&g_woL);
    __nv_bfloat16* wgH = (__nv_bfloat16*)sym(&g_wgH);
    __nv_bfloat16* wgL = (__nv_bfloat16*)sym(&g_wgL);
    __nv_bfloat16* wuH = (__nv_bfloat16*)sym(&g_wuH);
    __nv_bfloat16* wuL = (__nv_bfloat16*)sym(&g_wuL);
    __nv_bfloat16* wdH = (__nv_bfloat16*)sym(&g_wdH);
    __nv_bfloat16* wdL = (__nv_bfloat16*)sym(&g_wdL);

    const int TPB = 256;

    // 0: input RMSNorm (split output)
    rmsnorm_split<<<S, 256>>>(hidden, ln1_w, xnH, xnL);
    // 1-4: attention weight splits
    split_kernel<<<(C * C + TPB - 1) / TPB, TPB>>>(wq, wqH, wqL, C * C);
    split_kernel<<<(C * C + TPB - 1) / TPB, TPB>>>(wk, wkH, wkL, C * C);
    split_kernel<<<(C * C + TPB - 1) / TPB, TPB>>>(wv, wvH, wvL, C * C);
    split_kernel<<<(C * C + TPB - 1) / TPB, TPB>>>(wo, woH, woL, C * C);

    // 5: fused QKV projection (ncu -s 5 profiles this launch)
    dim3 gqkv3(3 * (C / 128), S / 128);
    gemm_split3<<<gqkv3, 256, GSMEM>>>(xnH, xnL, wqH, wqL, q, wkH, wkL, k,
                                       wvH, wvL, v, S, C, C, C / 128);

    // RoPE -> split bf16; V -> transposed split bf16
    dim3 grope(S, H);
    rope_split<<<grope, 64>>>(q, cosb, sinb, qH, qL, nullptr);
    rope_split<<<grope, 64>>>(k, cosb, sinb, kH, kL, k2);
    dim3 gvt(C / 32, S / 32);
    vt_split<<<gvt, dim3(32, 8)>>>(v, vtH, vtL);

    // tensor-core flash attention -> split bf16 ctx
    dim3 gattn(S / 128, H);
    attn_mma<<<gattn, 256, ASMEM>>>(qH, qL, kH, kL, vtH, vtL, k2, cH, cL);

    // output projection + residual
    dim3 gsq(C / 128, S / 128);
    gemm_split<<<gsq, 256, GSMEM>>>(cH, cL, woH, woL, hb, hidden, S, C, C);

    // post-attn RMSNorm
    rmsnorm_split<<<S, 256>>>(hb, ln2_w, yH, yL);

    // FFN weight splits
    split_kernel<<<(FF * C + TPB - 1) / TPB, TPB>>>(wg, wgH, wgL, FF * C);
    split_kernel<<<(FF * C + TPB - 1) / TPB, TPB>>>(wu, wuH, wuL, FF * C);
    split_kernel<<<(C * FF + TPB - 1) / TPB, TPB>>>(wd, wdH, wdL, C * FF);

    // fused FFN gate & up
    dim3 gff3(2 * (FF / 128), S / 128);
    gemm_split3<<<gff3, 256, GSMEM>>>(yH, yL, wgH, wgL, gate, wuH, wuL, up,
                                      wgH, wgL, gate, S, FF, C, FF / 128);

    // SiLU(gate)*up -> split
    silu_mul_split<<<(S * FF + TPB - 1) / TPB, TPB>>>(gate, up, aH, aL, S * FF);

    // down projection + residual -> final output
    gemm_split<<<gsq, 256, GSMEM>>>(aH, aL, wdH, wdL, out, hb, S, C, FF);
}